// round 10
// baseline (speedup 1.0000x reference)
#include <cuda_runtime.h>
#include <math.h>

#define B_ 8
#define SEQ 2048
#define DM 512
#define NH 8
#define DH 64
#define NL 3
#define UMAX 40
#define LNEPS 1e-5f

// ---------------- scratch ----------------
__device__ float g_x [B_*SEQ*DM];
__device__ float g_q [B_*SEQ*DM];
__device__ float g_k [B_*SEQ*DM];
__device__ float g_v [B_*SEQ*DM];
__device__ float g_t1[B_*SEQ*DM];
__device__ float g_t2[B_*SEQ*DM];
__device__ float g_M [B_*NH*SEQ];
__device__ int   g_idx[SEQ*UMAX];
__device__ int   g_top[B_*NH*UMAX];
__device__ float g_vm [B_*NH*DH];
__device__ float g_upd[B_*NH*UMAX*DH];
__device__ float g_red[B_*DM];
__device__ float g_base[B_*DM];

// ---------------- threefry2x32 (JAX-compatible) ----------------
__host__ __device__ __forceinline__ void tf2x32(unsigned k0, unsigned k1,
                                                unsigned x0, unsigned x1,
                                                unsigned* o0, unsigned* o1) {
    unsigned ks[3] = {k0, k1, k0 ^ k1 ^ 0x1BD11BDAu};
    x0 += ks[0]; x1 += ks[1];
    const int R0[4] = {13,15,26,6};
    const int R1[4] = {17,29,16,24};
    #pragma unroll
    for (int g = 0; g < 5; g++) {
        #pragma unroll
        for (int q = 0; q < 4; q++) {
            int r = (g & 1) ? R1[q] : R0[q];
            x0 += x1;
            x1 = (x1 << r) | (x1 >> (32 - r));
            x1 ^= x0;
        }
        x0 += ks[(g + 1) % 3];
        x1 += ks[(g + 2) % 3] + (unsigned)(g + 1);
    }
    *o0 = x0; *o1 = x1;
}

__global__ void idx_kernel(int* __restrict__ idx, int L, int U, unsigned k0, unsigned k1) {
    int f = blockIdx.x * blockDim.x + threadIdx.x;
    if (f >= L * U) return;
    unsigned o0, o1;
    tf2x32(k0, k1, 0u, (unsigned)f, &o0, &o1);
    idx[f] = (int)((o0 ^ o1) % (unsigned)L);
}

// ---------------- token embedding + positional encoding ----------------
__global__ void embed_kernel(const float* __restrict__ xe, const float* __restrict__ tw,
                             float* __restrict__ out) {
    int i = blockIdx.x * blockDim.x + threadIdx.x;
    if (i >= B_ * SEQ * DM) return;
    int c = i % DM;
    int l = (i / DM) % SEQ;
    int b = i / (DM * SEQ);
    int lm = (l == 0) ? SEQ - 1 : l - 1;
    int lp = (l == SEQ - 1) ? 0 : l + 1;
    float v = tw[c*3+0]*xe[b*SEQ+lm] + tw[c*3+1]*xe[b*SEQ+l] + tw[c*3+2]*xe[b*SEQ+lp];
    int i2 = c >> 1;
    float div = expf((float)(2*i2) * (-9.210340371976184f / 512.0f));
    float arg = (float)l * div;
    v += (c & 1) ? cosf(arg) : sinf(arg);
    out[i] = v;
}

// ---------------- SGEMM 128x128 tile, 8x8 microtile, double-buffered ----------------
#define SST 132
__device__ __forceinline__ void gemm_body(
    const float* __restrict__ A, const float* __restrict__ W,
    const float* __restrict__ bias, float* __restrict__ C,
    int M, int N, int K, int act)
{
    __shared__ float As[2][16][SST];
    __shared__ float Ws[2][16][SST];
    int bm = blockIdx.y * 128, bn = blockIdx.x * 128;
    int tid = threadIdx.x;
    int tx = tid & 15, ty = tid >> 4;
    int lr = tid >> 2;
    int lc = (tid & 3) << 2;
    const float* pa0 = A + (size_t)(bm + lr) * K + lc;
    const float* pa1 = A + (size_t)(bm + lr + 64) * K + lc;
    const float* pw0 = W + (size_t)(bn + lr) * K + lc;
    const float* pw1 = W + (size_t)(bn + lr + 64) * K + lc;
    float acc[8][8] = {};
    {
        float4 a0 = *(const float4*)pa0;
        float4 a1 = *(const float4*)pa1;
        float4 w0 = *(const float4*)pw0;
        float4 w1 = *(const float4*)pw1;
        As[0][lc+0][lr]    = a0.x; As[0][lc+1][lr]    = a0.y; As[0][lc+2][lr]    = a0.z; As[0][lc+3][lr]    = a0.w;
        As[0][lc+0][lr+64] = a1.x; As[0][lc+1][lr+64] = a1.y; As[0][lc+2][lr+64] = a1.z; As[0][lc+3][lr+64] = a1.w;
        Ws[0][lc+0][lr]    = w0.x; Ws[0][lc+1][lr]    = w0.y; Ws[0][lc+2][lr]    = w0.z; Ws[0][lc+3][lr]    = w0.w;
        Ws[0][lc+0][lr+64] = w1.x; Ws[0][lc+1][lr+64] = w1.y; Ws[0][lc+2][lr+64] = w1.z; Ws[0][lc+3][lr+64] = w1.w;
    }
    __syncthreads();
    int buf = 0;
    for (int k0 = 0; k0 < K; k0 += 16) {
        float4 a0n, a1n, w0n, w1n;
        bool pf = (k0 + 16) < K;
        if (pf) {
            a0n = *(const float4*)(pa0 + k0 + 16);
            a1n = *(const float4*)(pa1 + k0 + 16);
            w0n = *(const float4*)(pw0 + k0 + 16);
            w1n = *(const float4*)(pw1 + k0 + 16);
        }
        #pragma unroll
        for (int kk = 0; kk < 16; kk++) {
            float a[8], w[8];
            *(float4*)(a)     = *(const float4*)&As[buf][kk][ty << 2];
            *(float4*)(a + 4) = *(const float4*)&As[buf][kk][64 + (ty << 2)];
            *(float4*)(w)     = *(const float4*)&Ws[buf][kk][tx << 2];
            *(float4*)(w + 4) = *(const float4*)&Ws[buf][kk][64 + (tx << 2)];
            #pragma unroll
            for (int i = 0; i < 8; i++)
                #pragma unroll
                for (int j = 0; j < 8; j++)
                    acc[i][j] += a[i] * w[j];
        }
        if (pf) {
            int nb = buf ^ 1;
            As[nb][lc+0][lr]    = a0n.x; As[nb][lc+1][lr]    = a0n.y; As[nb][lc+2][lr]    = a0n.z; As[nb][lc+3][lr]    = a0n.w;
            As[nb][lc+0][lr+64] = a1n.x; As[nb][lc+1][lr+64] = a1n.y; As[nb][lc+2][lr+64] = a1n.z; As[nb][lc+3][lr+64] = a1n.w;
            Ws[nb][lc+0][lr]    = w0n.x; Ws[nb][lc+1][lr]    = w0n.y; Ws[nb][lc+2][lr]    = w0n.z; Ws[nb][lc+3][lr]    = w0n.w;
            Ws[nb][lc+0][lr+64] = w1n.x; Ws[nb][lc+1][lr+64] = w1n.y; Ws[nb][lc+2][lr+64] = w1n.z; Ws[nb][lc+3][lr+64] = w1n.w;
        }
        __syncthreads();
        buf ^= 1;
    }
    #pragma unroll
    for (int i = 0; i < 8; i++) {
        int m = bm + ((i < 4) ? ((ty << 2) + i) : (64 + (ty << 2) + i - 4));
        #pragma unroll
        for (int jh = 0; jh < 2; jh++) {
            int n = bn + jh * 64 + (tx << 2);
            float4 o;
            o.x = acc[i][jh*4+0] + bias[n+0];
            o.y = acc[i][jh*4+1] + bias[n+1];
            o.z = acc[i][jh*4+2] + bias[n+2];
            o.w = acc[i][jh*4+3] + bias[n+3];
            if (act) {
                o.x = 0.5f * o.x * (1.0f + erff(o.x * 0.7071067811865475f));
                o.y = 0.5f * o.y * (1.0f + erff(o.y * 0.7071067811865475f));
                o.z = 0.5f * o.z * (1.0f + erff(o.z * 0.7071067811865475f));
                o.w = 0.5f * o.w * (1.0f + erff(o.w * 0.7071067811865475f));
            }
            *(float4*)(C + (size_t)m * N + n) = o;
        }
    }
}

__global__ __launch_bounds__(256, 2) void gemm_kernel(
    const float* __restrict__ A, const float* __restrict__ W,
    const float* __restrict__ bias, float* __restrict__ C,
    int M, int N, int K, int act)
{
    gemm_body(A, W, bias, C, M, N, K, act);
}

__global__ __launch_bounds__(256, 2) void qkv_kernel(
    const float* __restrict__ A,
    const float* __restrict__ Wq, const float* __restrict__ Wk, const float* __restrict__ Wv,
    const float* __restrict__ bq, const float* __restrict__ bk, const float* __restrict__ bv,
    float* __restrict__ q, float* __restrict__ k, float* __restrict__ v,
    int M, int K)
{
    const float* W; const float* b; float* C;
    if (blockIdx.z == 0)      { W = Wq; b = bq; C = q; }
    else if (blockIdx.z == 1) { W = Wk; b = bk; C = k; }
    else                      { W = Wv; b = bv; C = v; }
    gemm_body(A, W, b, C, M, DM, K, 0);
}

// ---------------- distil conv as GEMM (K=3*DM, circular pad) + BN-affine + ELU ----------------
__global__ __launch_bounds__(256, 2) void convgemm_kernel(
    const float* __restrict__ X, const float* __restrict__ Wc,
    const float* __restrict__ cb, const float* __restrict__ gg,
    const float* __restrict__ be, float* __restrict__ C, int L)
{
    __shared__ float As[2][16][SST];
    __shared__ float Ws[2][16][SST];
    int bm = blockIdx.y * 128, bn = blockIdx.x * 128;
    int tid = threadIdx.x;
    int tx = tid & 15, ty = tid >> 4;
    int lr = tid >> 2;
    int lc = (tid & 3) << 2;
    int m0 = bm + lr,      b0 = m0 / L, l0 = m0 % L;
    int m1 = bm + lr + 64, b1 = m1 / L, l1 = m1 % L;
    int n0 = bn + lr, n1 = bn + lr + 64;
    float acc[8][8] = {};

    auto loadk = [&](int k0, float4& a0, float4& a1, float4& w0, float4& w1) {
        int kk = k0 + lc;
        int j = kk / DM;
        int i0 = kk - j * DM;
        int ls0 = l0 - 1 + j; if (ls0 < 0) ls0 += L; else if (ls0 >= L) ls0 -= L;
        int ls1 = l1 - 1 + j; if (ls1 < 0) ls1 += L; else if (ls1 >= L) ls1 -= L;
        a0 = *(const float4*)(X + (size_t)(b0 * L + ls0) * DM + i0);
        a1 = *(const float4*)(X + (size_t)(b1 * L + ls1) * DM + i0);
        w0.x = Wc[((size_t)n0 * DM + i0 + 0) * 3 + j];
        w0.y = Wc[((size_t)n0 * DM + i0 + 1) * 3 + j];
        w0.z = Wc[((size_t)n0 * DM + i0 + 2) * 3 + j];
        w0.w = Wc[((size_t)n0 * DM + i0 + 3) * 3 + j];
        w1.x = Wc[((size_t)n1 * DM + i0 + 0) * 3 + j];
        w1.y = Wc[((size_t)n1 * DM + i0 + 1) * 3 + j];
        w1.z = Wc[((size_t)n1 * DM + i0 + 2) * 3 + j];
        w1.w = Wc[((size_t)n1 * DM + i0 + 3) * 3 + j];
    };
    auto stores = [&](int nb, const float4& a0, const float4& a1,
                      const float4& w0, const float4& w1) {
        As[nb][lc+0][lr]    = a0.x; As[nb][lc+1][lr]    = a0.y; As[nb][lc+2][lr]    = a0.z; As[nb][lc+3][lr]    = a0.w;
        As[nb][lc+0][lr+64] = a1.x; As[nb][lc+1][lr+64] = a1.y; As[nb][lc+2][lr+64] = a1.z; As[nb][lc+3][lr+64] = a1.w;
        Ws[nb][lc+0][lr]    = w0.x; Ws[nb][lc+1][lr]    = w0.y; Ws[nb][lc+2][lr]    = w0.z; Ws[nb][lc+3][lr]    = w0.w;
        Ws[nb][lc+0][lr+64] = w1.x; Ws[nb][lc+1][lr+64] = w1.y; Ws[nb][lc+2][lr+64] = w1.z; Ws[nb][lc+3][lr+64] = w1.w;
    };

    {
        float4 a0, a1, w0, w1;
        loadk(0, a0, a1, w0, w1);
        stores(0, a0, a1, w0, w1);
    }
    __syncthreads();
    int buf = 0;
    for (int k0 = 0; k0 < 3 * DM; k0 += 16) {
        float4 a0n, a1n, w0n, w1n;
        bool pf = (k0 + 16) < 3 * DM;
        if (pf) loadk(k0 + 16, a0n, a1n, w0n, w1n);
        #pragma unroll
        for (int kk2 = 0; kk2 < 16; kk2++) {
            float a[8], w[8];
            *(float4*)(a)     = *(const float4*)&As[buf][kk2][ty << 2];
            *(float4*)(a + 4) = *(const float4*)&As[buf][kk2][64 + (ty << 2)];
            *(float4*)(w)     = *(const float4*)&Ws[buf][kk2][tx << 2];
            *(float4*)(w + 4) = *(const float4*)&Ws[buf][kk2][64 + (tx << 2)];
            #pragma unroll
            for (int i = 0; i < 8; i++)
                #pragma unroll
                for (int jj = 0; jj < 8; jj++)
                    acc[i][jj] += a[i] * w[jj];
        }
        if (pf) stores(buf ^ 1, a0n, a1n, w0n, w1n);
        __syncthreads();
        buf ^= 1;
    }
    const float invs = 0.9999950000374997f;
    #pragma unroll
    for (int i = 0; i < 8; i++) {
        int m = bm + ((i < 4) ? ((ty << 2) + i) : (64 + (ty << 2) + i - 4));
        #pragma unroll
        for (int jh = 0; jh < 2; jh++) {
            int n = bn + jh * 64 + (tx << 2);
            float4 o;
            float* po = &o.x;
            #pragma unroll
            for (int c4 = 0; c4 < 4; c4++) {
                float v = (acc[i][jh*4+c4] + cb[n+c4]) * invs * gg[n+c4] + be[n+c4];
                po[c4] = v > 0.0f ? v : expm1f(v);
            }
            *(float4*)(C + (size_t)m * DM + n) = o;
        }
    }
}

// maxpool kernel=3 stride=2 pad=1
__global__ void pool_kernel(const float* __restrict__ Y, float* __restrict__ X, int Lin) {
    int Lout = Lin >> 1;
    int i = blockIdx.x * blockDim.x + threadIdx.x;
    if (i >= B_ * Lout * DM) return;
    int c = i % DM;
    int lp = (i / DM) % Lout;
    int b = i / (DM * Lout);
    float mv = -INFINITY;
    #pragma unroll
    for (int j = 0; j < 3; j++) {
        int l = 2 * lp - 1 + j;
        if (l >= 0 && l < Lin) mv = fmaxf(mv, Y[(size_t)(b * Lin + l) * DM + c]);
    }
    X[(size_t)(b * Lout + lp) * DM + c] = mv;
}

// ---------------- sparsity measure: 2 queries per warp, float4 lanes, 4-shfl reduce ----------------
__global__ void m_kernel(const float* __restrict__ q, const float* __restrict__ k,
                         const int* __restrict__ idx, float* __restrict__ Mout,
                         int L, int U) {
    int gw = (blockIdx.x * blockDim.x + threadIdx.x) >> 5;
    int lane = threadIdx.x & 31;
    int half = lane >> 4;
    int lane4 = lane & 15;
    int qi = gw * 2 + half;
    if (qi >= B_ * NH * L) return;
    int l = qi % L;
    int bh = qi / L;
    int h = bh % NH, b = bh / NH;
    float4 q4 = ((const float4*)(q + (size_t)(b * L + l) * DM + h * DH))[lane4];
    const int* ip = idx + l * U;
    const float* kh = k + h * DH;
    float mx = -INFINITY, sum = 0.0f;
    int ki0 = ip[0];
    int u = 0;
    for (; u + 2 <= U; u += 2) {
        int ki1 = ip[u + 1];
        float4 k40 = ((const float4*)(kh + (size_t)(b * L + ki0) * DM))[lane4];
        float4 k41 = ((const float4*)(kh + (size_t)(b * L + ki1) * DM))[lane4];
        if (u + 2 < U) ki0 = ip[u + 2];
        float p0 = q4.x*k40.x + q4.y*k40.y + q4.z*k40.z + q4.w*k40.w;
        float p1 = q4.x*k41.x + q4.y*k41.y + q4.z*k41.z + q4.w*k41.w;
        p0 += __shfl_xor_sync(0xffffffffu, p0, 8);
        p1 += __shfl_xor_sync(0xffffffffu, p1, 8);
        p0 += __shfl_xor_sync(0xffffffffu, p0, 4);
        p1 += __shfl_xor_sync(0xffffffffu, p1, 4);
        p0 += __shfl_xor_sync(0xffffffffu, p0, 2);
        p1 += __shfl_xor_sync(0xffffffffu, p1, 2);
        p0 += __shfl_xor_sync(0xffffffffu, p0, 1);
        p1 += __shfl_xor_sync(0xffffffffu, p1, 1);
        mx = fmaxf(mx, fmaxf(p0, p1));
        sum += p0 + p1;
    }
    if (u < U) {
        float4 k40 = ((const float4*)(kh + (size_t)(b * L + ki0) * DM))[lane4];
        float p0 = q4.x*k40.x + q4.y*k40.y + q4.z*k40.z + q4.w*k40.w;
        p0 += __shfl_xor_sync(0xffffffffu, p0, 8);
        p0 += __shfl_xor_sync(0xffffffffu, p0, 4);
        p0 += __shfl_xor_sync(0xffffffffu, p0, 2);
        p0 += __shfl_xor_sync(0xffffffffu, p0, 1);
        mx = fmaxf(mx, p0);
        sum += p0;
    }
    if (lane4 == 0) Mout[bh * L + l] = mx - sum / (float)U;
}

// ---------------- top-U selection ----------------
__global__ void topk_kernel(const float* __restrict__ Mv, int* __restrict__ top, int L, int U) {
    __shared__ float sm[2048];
    __shared__ float rv[256];
    __shared__ int   ri[256];
    int bh = blockIdx.x, tid = threadIdx.x;
    const float* row = Mv + bh * L;
    for (int l = tid; l < L; l += 256) sm[l] = row[l];
    __syncthreads();
    for (int it = 0; it < U; it++) {
        float bv = -INFINITY; int bi = 0x7fffffff;
        for (int l = tid; l < L; l += 256) {
            float v = sm[l];
            if (v > bv || (v == bv && l < bi)) { bv = v; bi = l; }
        }
        rv[tid] = bv; ri[tid] = bi;
        __syncthreads();
        for (int s = 128; s > 0; s >>= 1) {
            if (tid < s) {
                if (rv[tid+s] > rv[tid] || (rv[tid+s] == rv[tid] && ri[tid+s] < ri[tid])) {
                    rv[tid] = rv[tid+s]; ri[tid] = ri[tid+s];
                }
            }
            __syncthreads();
        }
        if (tid == 0) { top[bh * U + it] = ri[0]; sm[ri[0]] = -INFINITY; }
        __syncthreads();
    }
}

__global__ void vmean_kernel(const float* __restrict__ v, float* __restrict__ vm, int L) {
    __shared__ float sred[256];
    int bh = blockIdx.x;
    int h = bh % NH, b = bh / NH;
    int tid = threadIdx.x;
    int d = tid & 63, part = tid >> 6;
    int chunk = L >> 2;
    float acc = 0.0f;
    for (int l = part * chunk; l < (part + 1) * chunk; l++)
        acc += v[(size_t)(b * L + l) * DM + h * DH + d];
    sred[tid] = acc;
    __syncthreads();
    if (tid < 128) sred[tid] += sred[tid + 128];
    __syncthreads();
    if (tid < 64) vm[bh * DH + tid] = (sred[tid] + sred[tid + 64]) / (float)L;
}

// ---------------- full softmax attention for the U selected queries ----------------
__global__ void attn_kernel(const float* __restrict__ q, const float* __restrict__ k,
                            const float* __restrict__ v, const int* __restrict__ top,
                            float* __restrict__ upd, int L, int U) {
    __shared__ float qs[64];
    __shared__ float s[2048];
    __shared__ float red[128];
    int bhu = blockIdx.x;
    int u = bhu % U;
    int bh = bhu / U;
    int h = bh % NH, b = bh / NH;
    int tid = threadIdx.x; // 128
    int lq = top[bh * U + u];
    if (tid < 64) qs[tid] = q[(size_t)(b * L + lq) * DM + h * DH + tid];
    __syncthreads();
    float lmax = -INFINITY;
    const float4* qs4 = (const float4*)qs;
    for (int l = tid; l < L; l += 128) {
        const float4* kp4 = (const float4*)(k + (size_t)(b * L + l) * DM + h * DH);
        float acc = 0.0f;
        #pragma unroll
        for (int d4 = 0; d4 < 16; d4++) {
            float4 kk = kp4[d4], qq = qs4[d4];
            acc += qq.x*kk.x + qq.y*kk.y + qq.z*kk.z + qq.w*kk.w;
        }
        acc *= 0.125f;
        s[l] = acc;
        lmax = fmaxf(lmax, acc);
    }
    red[tid] = lmax; __syncthreads();
    for (int st = 64; st; st >>= 1) { if (tid < st) red[tid] = fmaxf(red[tid], red[tid+st]); __syncthreads(); }
    float mx = red[0]; __syncthreads();
    float lsum = 0.0f;
    for (int l = tid; l < L; l += 128) { float e = expf(s[l] - mx); s[l] = e; lsum += e; }
    red[tid] = lsum; __syncthreads();
    for (int st = 64; st; st >>= 1) { if (tid < st) red[tid] += red[tid+st]; __syncthreads(); }
    float ssum = red[0]; __syncthreads();
    int d = tid & 63, half = tid >> 6;
    int l0 = half * (L >> 1), l1 = l0 + (L >> 1);
    float acc = 0.0f;
    for (int l = l0; l < l1; l++) acc += s[l] * v[(size_t)(b * L + l) * DM + h * DH + d];
    red[tid] = acc; __syncthreads();
    if (tid < 64) upd[(size_t)(bh * U + u) * DH + tid] = (red[tid] + red[tid + 64]) / ssum;
}

// ---------------- Wo projection via base + low-rank corrections ----------------
// base[b][n] = bo[n] + sum_c vmcat[b][c] * Wo[n][c]   (vm is [b][h][d] = contiguous [b][c])
__global__ void obase_kernel(const float* __restrict__ vm, const float* __restrict__ Wo,
                             const float* __restrict__ bo, float* __restrict__ base) {
    __shared__ float vs[DM];
    int b = blockIdx.x, n = threadIdx.x; // 512 threads
    vs[n] = vm[b * DM + n];
    __syncthreads();
    const float* w = Wo + (size_t)n * DM;
    float acc = 0.0f;
    #pragma unroll 8
    for (int c = 0; c < DM; c++) acc += vs[c] * w[c];
    base[b * DM + n] = acc + bo[n];
}

// t1[b,l][n] = base[b][n]
__global__ void ofill_kernel(const float* __restrict__ base, float* __restrict__ t1, int L) {
    int i = blockIdx.x * blockDim.x + threadIdx.x;
    if (i >= B_ * L * DM) return;
    int n = i % DM;
    int b = i / (DM * L);
    t1[i] = base[b * DM + n];
}

// t1[b,top[bh,u]][n] += sum_d (upd-vm)[d] * Wo[n][h*64+d]
__global__ void ocorr_kernel(const float* __restrict__ upd, const float* __restrict__ vm,
                             const float* __restrict__ Wo, const int* __restrict__ top,
                             float* __restrict__ t1, int L, int U) {
    __shared__ float dlt[DH];
    int bhu = blockIdx.x;
    int u = bhu % U, bh = bhu / U;
    int h = bh % NH, b = bh / NH;
    int l = top[bh * U + u];
    int tid = threadIdx.x; // 128
    if (tid < DH) dlt[tid] = upd[(size_t)bhu * DH + tid] - vm[bh * DH + tid];
    __syncthreads();
    float* row = t1 + (size_t)(b * L + l) * DM;
    for (int n = tid; n < DM; n += 128) {
        const float* w = Wo + (size_t)n * DM + h * DH;
        float acc = 0.0f;
        #pragma unroll
        for (int d = 0; d < DH; d++) acc += dlt[d] * w[d];
        atomicAdd(&row[n], acc);
    }
}

// ---------------- x = LayerNorm(x + t) ----------------
__global__ void addln_kernel(float* __restrict__ x, const float* __restrict__ t,
                             const float* __restrict__ g, const float* __restrict__ bb) {
    __shared__ float row[512];
    __shared__ float red[256];
    size_t r = blockIdx.x;
    int tid = threadIdx.x;
    float v0 = x[r * 512 + tid]       + (t ? t[r * 512 + tid]       : 0.0f);
    float v1 = x[r * 512 + tid + 256] + (t ? t[r * 512 + tid + 256] : 0.0f);
    row[tid] = v0; row[tid + 256] = v1;
    red[tid] = v0 + v1;
    __syncthreads();
    for (int s = 128; s; s >>= 1) { if (tid < s) red[tid] += red[tid + s]; __syncthreads(); }
    float mu = red[0] * (1.0f / 512.0f);
    __syncthreads();
    float d0 = row[tid] - mu, d1 = row[tid + 256] - mu;
    red[tid] = d0 * d0 + d1 * d1;
    __syncthreads();
    for (int s = 128; s; s >>= 1) { if (tid < s) red[tid] += red[tid + s]; __syncthreads(); }
    float rstd = rsqrtf(red[0] * (1.0f / 512.0f) + LNEPS);
    x[r * 512 + tid]       = d0 * rstd * g[tid]       + bb[tid];
    x[r * 512 + tid + 256] = d1 * rstd * g[tid + 256] + bb[tid + 256];
}

__global__ void rowmax_kernel(const float* __restrict__ x, float* __restrict__ outr, int L) {
    int b = blockIdx.x, c = threadIdx.x;
    float m = -INFINITY;
    for (int l = 0; l < L; l++) m = fmaxf(m, x[(size_t)(b * L + l) * DM + c]);
    outr[b * DM + c] = m;
}

__global__ void proj_kernel(const float* __restrict__ red, const float* __restrict__ pw,
                            const float* __restrict__ pb, float* __restrict__ out) {
    int w = threadIdx.x >> 5, lane = threadIdx.x & 31;
    int b = w >> 1, o = w & 1;
    float acc = 0.0f;
    for (int c = lane; c < DM; c += 32) acc += red[b * DM + c] * pw[o * DM + c];
    #pragma unroll
    for (int s = 16; s; s >>= 1) acc += __shfl_xor_sync(0xffffffffu, acc, s);
    if (lane == 0) out[b * 2 + o] = acc + pb[o];
}

// ---------------- host ----------------
extern "C" void kernel_launch(void* const* d_in, const int* in_sizes, int n_in,
                              void* d_out, int out_size) {
    (void)n_in; (void)out_size;
    const float* x_enc = (const float*)d_in[0];
    const float* tok_w = (const float*)d_in[1];
    const float *Wq, *Wk, *Wv, *Wo, *bq, *bk, *bv, *bo;
    if (in_sizes[5] > 10000) {
        Wq = (const float*)d_in[2]; Wk = (const float*)d_in[3];
        Wv = (const float*)d_in[4]; Wo = (const float*)d_in[5];
        bq = (const float*)d_in[6]; bk = (const float*)d_in[7];
        bv = (const float*)d_in[8]; bo = (const float*)d_in[9];
    } else {
        Wq = (const float*)d_in[2]; Wk = (const float*)d_in[3];
        Wv = (const float*)d_in[4]; bq = (const float*)d_in[5];
        bk = (const float*)d_in[6]; bv = (const float*)d_in[7];
        Wo = (const float*)d_in[8]; bo = (const float*)d_in[9];
    }
    const float* W1   = (const float*)d_in[10];
    const float* b1   = (const float*)d_in[11];
    const float* W2   = (const float*)d_in[12];
    const float* b2   = (const float*)d_in[13];
    const float* ln1g = (const float*)d_in[14];
    const float* ln1b = (const float*)d_in[15];
    const float* ln2g = (const float*)d_in[16];
    const float* ln2b = (const float*)d_in[17];
    const float* dcw  = (const float*)d_in[18];
    const float* dcb  = (const float*)d_in[19];
    const float* bng  = (const float*)d_in[20];
    const float* bnb  = (const float*)d_in[21];
    const float* lnfg = (const float*)d_in[22];
    const float* lnfb = (const float*)d_in[23];
    const float* pw   = (const float*)d_in[24];
    const float* pb   = (const float*)d_in[25];

    float *x, *q, *k, *v, *t1, *t2, *Mb, *vm, *upd, *redb, *baseb;
    int *idxb, *topb;
    cudaGetSymbolAddress((void**)&x,    g_x);
    cudaGetSymbolAddress((void**)&q,    g_q);
    cudaGetSymbolAddress((void**)&k,    g_k);
    cudaGetSymbolAddress((void**)&v,    g_v);
    cudaGetSymbolAddress((void**)&t1,   g_t1);
    cudaGetSymbolAddress((void**)&t2,   g_t2);
    cudaGetSymbolAddress((void**)&Mb,   g_M);
    cudaGetSymbolAddress((void**)&vm,   g_vm);
    cudaGetSymbolAddress((void**)&upd,  g_upd);
    cudaGetSymbolAddress((void**)&redb, g_red);
    cudaGetSymbolAddress((void**)&baseb,g_base);
    cudaGetSymbolAddress((void**)&idxb, g_idx);
    cudaGetSymbolAddress((void**)&topb, g_top);

    embed_kernel<<<(B_*SEQ*DM + 255) / 256, 256>>>(x_enc, tok_w, x);

    int L = SEQ;
    for (int i = 0; i < NL; i++) {
        int Mrows = B_ * L;
        dim3 gg(DM / 128, Mrows / 128);
        dim3 g3(DM / 128, Mrows / 128, 3);
        qkv_kernel<<<g3, 256>>>(x, Wq + i*DM*DM, Wk + i*DM*DM, Wv + i*DM*DM,
                                bq + i*DM, bk + i*DM, bv + i*DM,
                                q, k, v, Mrows, DM);

        int U = 5 * (int)ceil(log((double)L));
        if (U > L) U = L;

        unsigned f0, f1, c0, c1;
        tf2x32(0u, 42u, 0u, (unsigned)i, &f0, &f1);
        tf2x32(f0, f1, 0u, 1u, &c0, &c1);

        idx_kernel<<<(L*U + 255) / 256, 256>>>(idxb, L, U, c0, c1);
        m_kernel<<<(B_*NH*L/2*32 + 127) / 128, 128>>>(q, k, idxb, Mb, L, U);
        topk_kernel<<<B_*NH, 256>>>(Mb, topb, L, U);
        vmean_kernel<<<B_*NH, 256>>>(v, vm, L);
        attn_kernel<<<B_*NH*U, 128>>>(q, k, v, topb, upd, L, U);

        // o @ Wo^T + bo  ==  broadcast(vmcat_b @ Wo^T + bo)  +  scatter((upd-vm) @ Wo_h^T)
        obase_kernel<<<B_, 512>>>(vm, Wo + i*DM*DM, bo + i*DM, baseb);
        ofill_kernel<<<(B_*L*DM + 255) / 256, 256>>>(baseb, t1, L);
        ocorr_kernel<<<B_*NH*U, 128>>>(upd, vm, Wo + i*DM*DM, topb, t1, L, U);

        addln_kernel<<<Mrows, 256>>>(x, t1, ln1g + i*DM, ln1b + i*DM);
        gemm_kernel<<<gg, 256>>>(x, W1 + i*DM*DM, b1 + i*DM, t1, Mrows, DM, DM, 1);
        gemm_kernel<<<gg, 256>>>(t1, W2 + i*DM*DM, b2 + i*DM, t2, Mrows, DM, DM, 0);
        addln_kernel<<<Mrows, 256>>>(x, t2, ln2g + i*DM, ln2b + i*DM);

        if (i < NL - 1) {
            convgemm_kernel<<<gg, 256>>>(x, dcw + (size_t)i*DM*DM*3, dcb + i*DM,
                                         bng + i*DM, bnb + i*DM, t1, L);
            int Lout = L / 2;
            pool_kernel<<<(B_*Lout*DM + 255) / 256, 256>>>(t1, x, L);
            L = Lout;
        }
    }

    addln_kernel<<<B_*L, 256>>>(x, (const float*)nullptr, lnfg, lnfb);
    rowmax_kernel<<<B_, 512>>>(x, redb, L);
    proj_kernel<<<1, 512>>>(redb, pw, pb, (float*)d_out);
}

// round 11
// speedup vs baseline: 1.1978x; 1.1978x over previous
#include <cuda_runtime.h>
#include <math.h>

#define B_ 8
#define SEQ 2048
#define DM 512
#define NH 8
#define DH 64
#define NL 3
#define UMAX 40
#define LNEPS 1e-5f

// ---------------- scratch ----------------
__device__ float g_x [B_*SEQ*DM];
__device__ float g_q [B_*SEQ*DM];
__device__ float g_k [B_*SEQ*DM];
__device__ float g_v [B_*SEQ*DM];
__device__ float g_o [B_*SEQ*DM];
__device__ float g_t1[B_*SEQ*DM];
__device__ float g_t2[B_*SEQ*DM];
__device__ float g_M [B_*NH*SEQ];
__device__ int   g_idx[SEQ*UMAX];
__device__ int   g_top[B_*NH*UMAX];
__device__ float g_vm [B_*NH*DH];
__device__ float g_upd[B_*NH*UMAX*DH];
__device__ float g_red[B_*DM];

// ---------------- threefry2x32 (JAX-compatible) ----------------
__host__ __device__ __forceinline__ void tf2x32(unsigned k0, unsigned k1,
                                                unsigned x0, unsigned x1,
                                                unsigned* o0, unsigned* o1) {
    unsigned ks[3] = {k0, k1, k0 ^ k1 ^ 0x1BD11BDAu};
    x0 += ks[0]; x1 += ks[1];
    const int R0[4] = {13,15,26,6};
    const int R1[4] = {17,29,16,24};
    #pragma unroll
    for (int g = 0; g < 5; g++) {
        #pragma unroll
        for (int q = 0; q < 4; q++) {
            int r = (g & 1) ? R1[q] : R0[q];
            x0 += x1;
            x1 = (x1 << r) | (x1 >> (32 - r));
            x1 ^= x0;
        }
        x0 += ks[(g + 1) % 3];
        x1 += ks[(g + 2) % 3] + (unsigned)(g + 1);
    }
    *o0 = x0; *o1 = x1;
}

__global__ void idx_kernel(int* __restrict__ idx, int L, int U, unsigned k0, unsigned k1) {
    int f = blockIdx.x * blockDim.x + threadIdx.x;
    if (f >= L * U) return;
    unsigned o0, o1;
    tf2x32(k0, k1, 0u, (unsigned)f, &o0, &o1);
    idx[f] = (int)((o0 ^ o1) % (unsigned)L);
}

// ---------------- token embedding + positional encoding ----------------
__global__ void embed_kernel(const float* __restrict__ xe, const float* __restrict__ tw,
                             float* __restrict__ out) {
    int i = blockIdx.x * blockDim.x + threadIdx.x;
    if (i >= B_ * SEQ * DM) return;
    int c = i % DM;
    int l = (i / DM) % SEQ;
    int b = i / (DM * SEQ);
    int lm = (l == 0) ? SEQ - 1 : l - 1;
    int lp = (l == SEQ - 1) ? 0 : l + 1;
    float v = tw[c*3+0]*xe[b*SEQ+lm] + tw[c*3+1]*xe[b*SEQ+l] + tw[c*3+2]*xe[b*SEQ+lp];
    int i2 = c >> 1;
    float div = expf((float)(2*i2) * (-9.210340371976184f / 512.0f));
    float arg = (float)l * div;
    v += (c & 1) ? cosf(arg) : sinf(arg);
    out[i] = v;
}

// ---------------- SGEMM 128x128 tile, 8x8 microtile, double-buffered ----------------
#define SST 132
__device__ __forceinline__ void gemm_body(
    const float* __restrict__ A, const float* __restrict__ W,
    const float* __restrict__ bias, float* __restrict__ C,
    int M, int N, int K, int act)
{
    __shared__ float As[2][16][SST];
    __shared__ float Ws[2][16][SST];
    int bm = blockIdx.y * 128, bn = blockIdx.x * 128;
    int tid = threadIdx.x;
    int tx = tid & 15, ty = tid >> 4;
    int lr = tid >> 2;
    int lc = (tid & 3) << 2;
    const float* pa0 = A + (size_t)(bm + lr) * K + lc;
    const float* pa1 = A + (size_t)(bm + lr + 64) * K + lc;
    const float* pw0 = W + (size_t)(bn + lr) * K + lc;
    const float* pw1 = W + (size_t)(bn + lr + 64) * K + lc;
    float acc[8][8] = {};
    {
        float4 a0 = *(const float4*)pa0;
        float4 a1 = *(const float4*)pa1;
        float4 w0 = *(const float4*)pw0;
        float4 w1 = *(const float4*)pw1;
        As[0][lc+0][lr]    = a0.x; As[0][lc+1][lr]    = a0.y; As[0][lc+2][lr]    = a0.z; As[0][lc+3][lr]    = a0.w;
        As[0][lc+0][lr+64] = a1.x; As[0][lc+1][lr+64] = a1.y; As[0][lc+2][lr+64] = a1.z; As[0][lc+3][lr+64] = a1.w;
        Ws[0][lc+0][lr]    = w0.x; Ws[0][lc+1][lr]    = w0.y; Ws[0][lc+2][lr]    = w0.z; Ws[0][lc+3][lr]    = w0.w;
        Ws[0][lc+0][lr+64] = w1.x; Ws[0][lc+1][lr+64] = w1.y; Ws[0][lc+2][lr+64] = w1.z; Ws[0][lc+3][lr+64] = w1.w;
    }
    __syncthreads();
    int buf = 0;
    for (int k0 = 0; k0 < K; k0 += 16) {
        float4 a0n, a1n, w0n, w1n;
        bool pf = (k0 + 16) < K;
        if (pf) {
            a0n = *(const float4*)(pa0 + k0 + 16);
            a1n = *(const float4*)(pa1 + k0 + 16);
            w0n = *(const float4*)(pw0 + k0 + 16);
            w1n = *(const float4*)(pw1 + k0 + 16);
        }
        #pragma unroll
        for (int kk = 0; kk < 16; kk++) {
            float a[8], w[8];
            *(float4*)(a)     = *(const float4*)&As[buf][kk][ty << 2];
            *(float4*)(a + 4) = *(const float4*)&As[buf][kk][64 + (ty << 2)];
            *(float4*)(w)     = *(const float4*)&Ws[buf][kk][tx << 2];
            *(float4*)(w + 4) = *(const float4*)&Ws[buf][kk][64 + (tx << 2)];
            #pragma unroll
            for (int i = 0; i < 8; i++)
                #pragma unroll
                for (int j = 0; j < 8; j++)
                    acc[i][j] += a[i] * w[j];
        }
        if (pf) {
            int nb = buf ^ 1;
            As[nb][lc+0][lr]    = a0n.x; As[nb][lc+1][lr]    = a0n.y; As[nb][lc+2][lr]    = a0n.z; As[nb][lc+3][lr]    = a0n.w;
            As[nb][lc+0][lr+64] = a1n.x; As[nb][lc+1][lr+64] = a1n.y; As[nb][lc+2][lr+64] = a1n.z; As[nb][lc+3][lr+64] = a1n.w;
            Ws[nb][lc+0][lr]    = w0n.x; Ws[nb][lc+1][lr]    = w0n.y; Ws[nb][lc+2][lr]    = w0n.z; Ws[nb][lc+3][lr]    = w0n.w;
            Ws[nb][lc+0][lr+64] = w1n.x; Ws[nb][lc+1][lr+64] = w1n.y; Ws[nb][lc+2][lr+64] = w1n.z; Ws[nb][lc+3][lr+64] = w1n.w;
        }
        __syncthreads();
        buf ^= 1;
    }
    #pragma unroll
    for (int i = 0; i < 8; i++) {
        int m = bm + ((i < 4) ? ((ty << 2) + i) : (64 + (ty << 2) + i - 4));
        #pragma unroll
        for (int jh = 0; jh < 2; jh++) {
            int n = bn + jh * 64 + (tx << 2);
            float4 o;
            o.x = acc[i][jh*4+0] + bias[n+0];
            o.y = acc[i][jh*4+1] + bias[n+1];
            o.z = acc[i][jh*4+2] + bias[n+2];
            o.w = acc[i][jh*4+3] + bias[n+3];
            if (act) {
                o.x = 0.5f * o.x * (1.0f + erff(o.x * 0.7071067811865475f));
                o.y = 0.5f * o.y * (1.0f + erff(o.y * 0.7071067811865475f));
                o.z = 0.5f * o.z * (1.0f + erff(o.z * 0.7071067811865475f));
                o.w = 0.5f * o.w * (1.0f + erff(o.w * 0.7071067811865475f));
            }
            *(float4*)(C + (size_t)m * N + n) = o;
        }
    }
}

__global__ __launch_bounds__(256, 2) void gemm_kernel(
    const float* __restrict__ A, const float* __restrict__ W,
    const float* __restrict__ bias, float* __restrict__ C,
    int M, int N, int K, int act)
{
    gemm_body(A, W, bias, C, M, N, K, act);
}

__global__ __launch_bounds__(256, 2) void qkv_kernel(
    const float* __restrict__ A,
    const float* __restrict__ Wq, const float* __restrict__ Wk, const float* __restrict__ Wv,
    const float* __restrict__ bq, const float* __restrict__ bk, const float* __restrict__ bv,
    float* __restrict__ q, float* __restrict__ k, float* __restrict__ v,
    int M, int K)
{
    const float* W; const float* b; float* C;
    if (blockIdx.z == 0)      { W = Wq; b = bq; C = q; }
    else if (blockIdx.z == 1) { W = Wk; b = bk; C = k; }
    else                      { W = Wv; b = bv; C = v; }
    gemm_body(A, W, b, C, M, DM, K, 0);
}

// ---------------- distil conv as GEMM (K=3*DM, circular pad) + BN-affine + ELU ----------------
__global__ __launch_bounds__(256, 2) void convgemm_kernel(
    const float* __restrict__ X, const float* __restrict__ Wc,
    const float* __restrict__ cb, const float* __restrict__ gg,
    const float* __restrict__ be, float* __restrict__ C, int L)
{
    __shared__ float As[2][16][SST];
    __shared__ float Ws[2][16][SST];
    int bm = blockIdx.y * 128, bn = blockIdx.x * 128;
    int tid = threadIdx.x;
    int tx = tid & 15, ty = tid >> 4;
    int lr = tid >> 2;
    int lc = (tid & 3) << 2;
    int m0 = bm + lr,      b0 = m0 / L, l0 = m0 % L;
    int m1 = bm + lr + 64, b1 = m1 / L, l1 = m1 % L;
    int n0 = bn + lr, n1 = bn + lr + 64;
    float acc[8][8] = {};

    auto loadk = [&](int k0, float4& a0, float4& a1, float4& w0, float4& w1) {
        int kk = k0 + lc;
        int j = kk / DM;
        int i0 = kk - j * DM;
        int ls0 = l0 - 1 + j; if (ls0 < 0) ls0 += L; else if (ls0 >= L) ls0 -= L;
        int ls1 = l1 - 1 + j; if (ls1 < 0) ls1 += L; else if (ls1 >= L) ls1 -= L;
        a0 = *(const float4*)(X + (size_t)(b0 * L + ls0) * DM + i0);
        a1 = *(const float4*)(X + (size_t)(b1 * L + ls1) * DM + i0);
        w0.x = Wc[((size_t)n0 * DM + i0 + 0) * 3 + j];
        w0.y = Wc[((size_t)n0 * DM + i0 + 1) * 3 + j];
        w0.z = Wc[((size_t)n0 * DM + i0 + 2) * 3 + j];
        w0.w = Wc[((size_t)n0 * DM + i0 + 3) * 3 + j];
        w1.x = Wc[((size_t)n1 * DM + i0 + 0) * 3 + j];
        w1.y = Wc[((size_t)n1 * DM + i0 + 1) * 3 + j];
        w1.z = Wc[((size_t)n1 * DM + i0 + 2) * 3 + j];
        w1.w = Wc[((size_t)n1 * DM + i0 + 3) * 3 + j];
    };
    auto stores = [&](int nb, const float4& a0, const float4& a1,
                      const float4& w0, const float4& w1) {
        As[nb][lc+0][lr]    = a0.x; As[nb][lc+1][lr]    = a0.y; As[nb][lc+2][lr]    = a0.z; As[nb][lc+3][lr]    = a0.w;
        As[nb][lc+0][lr+64] = a1.x; As[nb][lc+1][lr+64] = a1.y; As[nb][lc+2][lr+64] = a1.z; As[nb][lc+3][lr+64] = a1.w;
        Ws[nb][lc+0][lr]    = w0.x; Ws[nb][lc+1][lr]    = w0.y; Ws[nb][lc+2][lr]    = w0.z; Ws[nb][lc+3][lr]    = w0.w;
        Ws[nb][lc+0][lr+64] = w1.x; Ws[nb][lc+1][lr+64] = w1.y; Ws[nb][lc+2][lr+64] = w1.z; Ws[nb][lc+3][lr+64] = w1.w;
    };

    {
        float4 a0, a1, w0, w1;
        loadk(0, a0, a1, w0, w1);
        stores(0, a0, a1, w0, w1);
    }
    __syncthreads();
    int buf = 0;
    for (int k0 = 0; k0 < 3 * DM; k0 += 16) {
        float4 a0n, a1n, w0n, w1n;
        bool pf = (k0 + 16) < 3 * DM;
        if (pf) loadk(k0 + 16, a0n, a1n, w0n, w1n);
        #pragma unroll
        for (int kk2 = 0; kk2 < 16; kk2++) {
            float a[8], w[8];
            *(float4*)(a)     = *(const float4*)&As[buf][kk2][ty << 2];
            *(float4*)(a + 4) = *(const float4*)&As[buf][kk2][64 + (ty << 2)];
            *(float4*)(w)     = *(const float4*)&Ws[buf][kk2][tx << 2];
            *(float4*)(w + 4) = *(const float4*)&Ws[buf][kk2][64 + (tx << 2)];
            #pragma unroll
            for (int i = 0; i < 8; i++)
                #pragma unroll
                for (int jj = 0; jj < 8; jj++)
                    acc[i][jj] += a[i] * w[jj];
        }
        if (pf) stores(buf ^ 1, a0n, a1n, w0n, w1n);
        __syncthreads();
        buf ^= 1;
    }
    const float invs = 0.9999950000374997f;
    #pragma unroll
    for (int i = 0; i < 8; i++) {
        int m = bm + ((i < 4) ? ((ty << 2) + i) : (64 + (ty << 2) + i - 4));
        #pragma unroll
        for (int jh = 0; jh < 2; jh++) {
            int n = bn + jh * 64 + (tx << 2);
            float4 o;
            float* po = &o.x;
            #pragma unroll
            for (int c4 = 0; c4 < 4; c4++) {
                float v = (acc[i][jh*4+c4] + cb[n+c4]) * invs * gg[n+c4] + be[n+c4];
                po[c4] = v > 0.0f ? v : expm1f(v);
            }
            *(float4*)(C + (size_t)m * DM + n) = o;
        }
    }
}

// maxpool kernel=3 stride=2 pad=1
__global__ void pool_kernel(const float* __restrict__ Y, float* __restrict__ X, int Lin) {
    int Lout = Lin >> 1;
    int i = blockIdx.x * blockDim.x + threadIdx.x;
    if (i >= B_ * Lout * DM) return;
    int c = i % DM;
    int lp = (i / DM) % Lout;
    int b = i / (DM * Lout);
    float mv = -INFINITY;
    #pragma unroll
    for (int j = 0; j < 3; j++) {
        int l = 2 * lp - 1 + j;
        if (l >= 0 && l < Lin) mv = fmaxf(mv, Y[(size_t)(b * Lin + l) * DM + c]);
    }
    X[(size_t)(b * Lout + lp) * DM + c] = mv;
}

// ---------------- sparsity measure: 2 queries per warp, float4 lanes, 4-shfl reduce ----------------
__global__ void m_kernel(const float* __restrict__ q, const float* __restrict__ k,
                         const int* __restrict__ idx, float* __restrict__ Mout,
                         int L, int U) {
    int gw = (blockIdx.x * blockDim.x + threadIdx.x) >> 5;
    int lane = threadIdx.x & 31;
    int half = lane >> 4;
    int lane4 = lane & 15;
    int qi = gw * 2 + half;
    if (qi >= B_ * NH * L) return;
    int l = qi % L;
    int bh = qi / L;
    int h = bh % NH, b = bh / NH;
    float4 q4 = ((const float4*)(q + (size_t)(b * L + l) * DM + h * DH))[lane4];
    const int* ip = idx + l * U;
    const float* kh = k + h * DH;
    float mx = -INFINITY, sum = 0.0f;
    int ki0 = ip[0];
    int u = 0;
    for (; u + 2 <= U; u += 2) {
        int ki1 = ip[u + 1];
        float4 k40 = ((const float4*)(kh + (size_t)(b * L + ki0) * DM))[lane4];
        float4 k41 = ((const float4*)(kh + (size_t)(b * L + ki1) * DM))[lane4];
        if (u + 2 < U) ki0 = ip[u + 2];
        float p0 = q4.x*k40.x + q4.y*k40.y + q4.z*k40.z + q4.w*k40.w;
        float p1 = q4.x*k41.x + q4.y*k41.y + q4.z*k41.z + q4.w*k41.w;
        p0 += __shfl_xor_sync(0xffffffffu, p0, 8);
        p1 += __shfl_xor_sync(0xffffffffu, p1, 8);
        p0 += __shfl_xor_sync(0xffffffffu, p0, 4);
        p1 += __shfl_xor_sync(0xffffffffu, p1, 4);
        p0 += __shfl_xor_sync(0xffffffffu, p0, 2);
        p1 += __shfl_xor_sync(0xffffffffu, p1, 2);
        p0 += __shfl_xor_sync(0xffffffffu, p0, 1);
        p1 += __shfl_xor_sync(0xffffffffu, p1, 1);
        mx = fmaxf(mx, fmaxf(p0, p1));
        sum += p0 + p1;
    }
    if (u < U) {
        float4 k40 = ((const float4*)(kh + (size_t)(b * L + ki0) * DM))[lane4];
        float p0 = q4.x*k40.x + q4.y*k40.y + q4.z*k40.z + q4.w*k40.w;
        p0 += __shfl_xor_sync(0xffffffffu, p0, 8);
        p0 += __shfl_xor_sync(0xffffffffu, p0, 4);
        p0 += __shfl_xor_sync(0xffffffffu, p0, 2);
        p0 += __shfl_xor_sync(0xffffffffu, p0, 1);
        mx = fmaxf(mx, p0);
        sum += p0;
    }
    if (lane4 == 0) Mout[bh * L + l] = mx - sum / (float)U;
}

// ---------------- top-U selection ----------------
__global__ void topk_kernel(const float* __restrict__ Mv, int* __restrict__ top, int L, int U) {
    __shared__ float sm[2048];
    __shared__ float rv[256];
    __shared__ int   ri[256];
    int bh = blockIdx.x, tid = threadIdx.x;
    const float* row = Mv + bh * L;
    for (int l = tid; l < L; l += 256) sm[l] = row[l];
    __syncthreads();
    for (int it = 0; it < U; it++) {
        float bv = -INFINITY; int bi = 0x7fffffff;
        for (int l = tid; l < L; l += 256) {
            float v = sm[l];
            if (v > bv || (v == bv && l < bi)) { bv = v; bi = l; }
        }
        rv[tid] = bv; ri[tid] = bi;
        __syncthreads();
        for (int s = 128; s > 0; s >>= 1) {
            if (tid < s) {
                if (rv[tid+s] > rv[tid] || (rv[tid+s] == rv[tid] && ri[tid+s] < ri[tid])) {
                    rv[tid] = rv[tid+s]; ri[tid] = ri[tid+s];
                }
            }
            __syncthreads();
        }
        if (tid == 0) { top[bh * U + it] = ri[0]; sm[ri[0]] = -INFINITY; }
        __syncthreads();
    }
}

__global__ void vmean_kernel(const float* __restrict__ v, float* __restrict__ vm, int L) {
    __shared__ float sred[256];
    int bh = blockIdx.x;
    int h = bh % NH, b = bh / NH;
    int tid = threadIdx.x;
    int d = tid & 63, part = tid >> 6;
    int chunk = L >> 2;
    float acc = 0.0f;
    for (int l = part * chunk; l < (part + 1) * chunk; l++)
        acc += v[(size_t)(b * L + l) * DM + h * DH + d];
    sred[tid] = acc;
    __syncthreads();
    if (tid < 128) sred[tid] += sred[tid + 128];
    __syncthreads();
    if (tid < 64) vm[bh * DH + tid] = (sred[tid] + sred[tid + 64]) / (float)L;
}

// ---------------- full softmax attention for the U selected queries ----------------
__global__ void attn_kernel(const float* __restrict__ q, const float* __restrict__ k,
                            const float* __restrict__ v, const int* __restrict__ top,
                            float* __restrict__ upd, int L, int U) {
    __shared__ float qs[64];
    __shared__ float s[2048];
    __shared__ float red[128];
    int bhu = blockIdx.x;
    int u = bhu % U;
    int bh = bhu / U;
    int h = bh % NH, b = bh / NH;
    int tid = threadIdx.x; // 128
    int lq = top[bh * U + u];
    if (tid < 64) qs[tid] = q[(size_t)(b * L + lq) * DM + h * DH + tid];
    __syncthreads();
    float lmax = -INFINITY;
    const float4* qs4 = (const float4*)qs;
    for (int l = tid; l < L; l += 128) {
        const float4* kp4 = (const float4*)(k + (size_t)(b * L + l) * DM + h * DH);
        float acc = 0.0f;
        #pragma unroll
        for (int d4 = 0; d4 < 16; d4++) {
            float4 kk = kp4[d4], qq = qs4[d4];
            acc += qq.x*kk.x + qq.y*kk.y + qq.z*kk.z + qq.w*kk.w;
        }
        acc *= 0.125f;
        s[l] = acc;
        lmax = fmaxf(lmax, acc);
    }
    red[tid] = lmax; __syncthreads();
    for (int st = 64; st; st >>= 1) { if (tid < st) red[tid] = fmaxf(red[tid], red[tid+st]); __syncthreads(); }
    float mx = red[0]; __syncthreads();
    float lsum = 0.0f;
    for (int l = tid; l < L; l += 128) { float e = expf(s[l] - mx); s[l] = e; lsum += e; }
    red[tid] = lsum; __syncthreads();
    for (int st = 64; st; st >>= 1) { if (tid < st) red[tid] += red[tid+st]; __syncthreads(); }
    float ssum = red[0]; __syncthreads();
    int d = tid & 63, half = tid >> 6;
    int l0 = half * (L >> 1), l1 = l0 + (L >> 1);
    float acc = 0.0f;
    for (int l = l0; l < l1; l++) acc += s[l] * v[(size_t)(b * L + l) * DM + h * DH + d];
    red[tid] = acc; __syncthreads();
    if (tid < 64) upd[(size_t)(bh * U + u) * DH + tid] = (red[tid] + red[tid + 64]) / ssum;
}

__global__ void oinit_kernel(float* __restrict__ o, const float* __restrict__ vm, int L) {
    int i = blockIdx.x * blockDim.x + threadIdx.x;
    if (i >= B_ * L * DM) return;
    int c = i % DM;
    int b = i / (DM * L);
    o[i] = vm[(b * NH + (c >> 6)) * DH + (c & 63)];
}

__global__ void scatter_kernel(float* __restrict__ o, const float* __restrict__ upd,
                               const int* __restrict__ top, int L, int U) {
    int bhu = blockIdx.x, d = threadIdx.x;
    int u = bhu % U;
    int bh = bhu / U;
    int h = bh % NH, b = bh / NH;
    int l = top[bh * U + u];
    o[(size_t)(b * L + l) * DM + h * DH + d] = upd[(size_t)(bh * U + u) * DH + d];
}

// ---------------- x = LayerNorm(x + t) ----------------
__global__ void addln_kernel(float* __restrict__ x, const float* __restrict__ t,
                             const float* __restrict__ g, const float* __restrict__ bb) {
    __shared__ float row[512];
    __shared__ float red[256];
    size_t r = blockIdx.x;
    int tid = threadIdx.x;
    float v0 = x[r * 512 + tid]       + (t ? t[r * 512 + tid]       : 0.0f);
    float v1 = x[r * 512 + tid + 256] + (t ? t[r * 512 + tid + 256] : 0.0f);
    row[tid] = v0; row[tid + 256] = v1;
    red[tid] = v0 + v1;
    __syncthreads();
    for (int s = 128; s; s >>= 1) { if (tid < s) red[tid] += red[tid + s]; __syncthreads(); }
    float mu = red[0] * (1.0f / 512.0f);
    __syncthreads();
    float d0 = row[tid] - mu, d1 = row[tid + 256] - mu;
    red[tid] = d0 * d0 + d1 * d1;
    __syncthreads();
    for (int s = 128; s; s >>= 1) { if (tid < s) red[tid] += red[tid + s]; __syncthreads(); }
    float rstd = rsqrtf(red[0] * (1.0f / 512.0f) + LNEPS);
    x[r * 512 + tid]       = d0 * rstd * g[tid]       + bb[tid];
    x[r * 512 + tid + 256] = d1 * rstd * g[tid + 256] + bb[tid + 256];
}

__global__ void rowmax_kernel(const float* __restrict__ x, float* __restrict__ outr, int L) {
    int b = blockIdx.x, c = threadIdx.x;
    float m = -INFINITY;
    for (int l = 0; l < L; l++) m = fmaxf(m, x[(size_t)(b * L + l) * DM + c]);
    outr[b * DM + c] = m;
}

__global__ void proj_kernel(const float* __restrict__ red, const float* __restrict__ pw,
                            const float* __restrict__ pb, float* __restrict__ out) {
    int w = threadIdx.x >> 5, lane = threadIdx.x & 31;
    int b = w >> 1, o = w & 1;
    float acc = 0.0f;
    for (int c = lane; c < DM; c += 32) acc += red[b * DM + c] * pw[o * DM + c];
    #pragma unroll
    for (int s = 16; s; s >>= 1) acc += __shfl_xor_sync(0xffffffffu, acc, s);
    if (lane == 0) out[b * 2 + o] = acc + pb[o];
}

// ---------------- host ----------------
extern "C" void kernel_launch(void* const* d_in, const int* in_sizes, int n_in,
                              void* d_out, int out_size) {
    (void)n_in; (void)out_size;
    const float* x_enc = (const float*)d_in[0];
    const float* tok_w = (const float*)d_in[1];
    const float *Wq, *Wk, *Wv, *Wo, *bq, *bk, *bv, *bo;
    if (in_sizes[5] > 10000) {
        Wq = (const float*)d_in[2]; Wk = (const float*)d_in[3];
        Wv = (const float*)d_in[4]; Wo = (const float*)d_in[5];
        bq = (const float*)d_in[6]; bk = (const float*)d_in[7];
        bv = (const float*)d_in[8]; bo = (const float*)d_in[9];
    } else {
        Wq = (const float*)d_in[2]; Wk = (const float*)d_in[3];
        Wv = (const float*)d_in[4]; bq = (const float*)d_in[5];
        bk = (const float*)d_in[6]; bv = (const float*)d_in[7];
        Wo = (const float*)d_in[8]; bo = (const float*)d_in[9];
    }
    const float* W1   = (const float*)d_in[10];
    const float* b1   = (const float*)d_in[11];
    const float* W2   = (const float*)d_in[12];
    const float* b2   = (const float*)d_in[13];
    const float* ln1g = (const float*)d_in[14];
    const float* ln1b = (const float*)d_in[15];
    const float* ln2g = (const float*)d_in[16];
    const float* ln2b = (const float*)d_in[17];
    const float* dcw  = (const float*)d_in[18];
    const float* dcb  = (const float*)d_in[19];
    const float* bng  = (const float*)d_in[20];
    const float* bnb  = (const float*)d_in[21];
    const float* lnfg = (const float*)d_in[22];
    const float* lnfb = (const float*)d_in[23];
    const float* pw   = (const float*)d_in[24];
    const float* pb   = (const float*)d_in[25];

    float *x, *q, *k, *v, *o, *t1, *t2, *Mb, *vm, *upd, *redb;
    int *idxb, *topb;
    cudaGetSymbolAddress((void**)&x,    g_x);
    cudaGetSymbolAddress((void**)&q,    g_q);
    cudaGetSymbolAddress((void**)&k,    g_k);
    cudaGetSymbolAddress((void**)&v,    g_v);
    cudaGetSymbolAddress((void**)&o,    g_o);
    cudaGetSymbolAddress((void**)&t1,   g_t1);
    cudaGetSymbolAddress((void**)&t2,   g_t2);
    cudaGetSymbolAddress((void**)&Mb,   g_M);
    cudaGetSymbolAddress((void**)&vm,   g_vm);
    cudaGetSymbolAddress((void**)&upd,  g_upd);
    cudaGetSymbolAddress((void**)&redb, g_red);
    cudaGetSymbolAddress((void**)&idxb, g_idx);
    cudaGetSymbolAddress((void**)&topb, g_top);

    embed_kernel<<<(B_*SEQ*DM + 255) / 256, 256>>>(x_enc, tok_w, x);

    int L = SEQ;
    for (int i = 0; i < NL; i++) {
        int Mrows = B_ * L;
        dim3 gg(DM / 128, Mrows / 128);
        dim3 g3(DM / 128, Mrows / 128, 3);
        qkv_kernel<<<g3, 256>>>(x, Wq + i*DM*DM, Wk + i*DM*DM, Wv + i*DM*DM,
                                bq + i*DM, bk + i*DM, bv + i*DM,
                                q, k, v, Mrows, DM);

        int U = 5 * (int)ceil(log((double)L));
        if (U > L) U = L;

        unsigned f0, f1, c0, c1;
        tf2x32(0u, 42u, 0u, (unsigned)i, &f0, &f1);
        tf2x32(f0, f1, 0u, 1u, &c0, &c1);

        idx_kernel<<<(L*U + 255) / 256, 256>>>(idxb, L, U, c0, c1);
        m_kernel<<<(B_*NH*L/2*32 + 127) / 128, 128>>>(q, k, idxb, Mb, L, U);
        topk_kernel<<<B_*NH, 256>>>(Mb, topb, L, U);
        vmean_kernel<<<B_*NH, 256>>>(v, vm, L);
        attn_kernel<<<B_*NH*U, 128>>>(q, k, v, topb, upd, L, U);
        oinit_kernel<<<(B_*L*DM + 255) / 256, 256>>>(o, vm, L);
        scatter_kernel<<<B_*NH*U, 64>>>(o, upd, topb, L, U);

        gemm_kernel<<<gg, 256>>>(o, Wo + i*DM*DM, bo + i*DM, t1, Mrows, DM, DM, 0);
        addln_kernel<<<Mrows, 256>>>(x, t1, ln1g + i*DM, ln1b + i*DM);
        gemm_kernel<<<gg, 256>>>(x, W1 + i*DM*DM, b1 + i*DM, t1, Mrows, DM, DM, 1);
        gemm_kernel<<<gg, 256>>>(t1, W2 + i*DM*DM, b2 + i*DM, t2, Mrows, DM, DM, 0);
        addln_kernel<<<Mrows, 256>>>(x, t2, ln2g + i*DM, ln2b + i*DM);

        if (i < NL - 1) {
            convgemm_kernel<<<gg, 256>>>(x, dcw + (size_t)i*DM*DM*3, dcb + i*DM,
                                         bng + i*DM, bnb + i*DM, t1, L);
            int Lout = L / 2;
            pool_kernel<<<(B_*Lout*DM + 255) / 256, 256>>>(t1, x, L);
            L = Lout;
        }
    }

    addln_kernel<<<B_*L, 256>>>(x, (const float*)nullptr, lnfg, lnfb);
    rowmax_kernel<<<B_, 512>>>(x, redb, L);
    proj_kernel<<<1, 512>>>(redb, pw, pb, (float*)d_out);
}

// round 12
// speedup vs baseline: 1.2625x; 1.0540x over previous
#include <cuda_runtime.h>
#include <math.h>

#define B_ 8
#define SEQ 2048
#define DM 512
#define NH 8
#define DH 64
#define NL 3
#define UMAX 40
#define UB 4
#define LNEPS 1e-5f

// ---------------- scratch ----------------
__device__ float g_x [B_*SEQ*DM];
__device__ float g_q [B_*SEQ*DM];
__device__ float g_k [B_*SEQ*DM];
__device__ float g_v [B_*SEQ*DM];
__device__ float g_o [B_*SEQ*DM];
__device__ float g_t1[B_*SEQ*DM];
__device__ float g_t2[B_*SEQ*DM];   // also reused as transposed conv weights (3*DM*DM floats)
__device__ float g_M [B_*NH*SEQ];
__device__ int   g_idx[SEQ*UMAX];
__device__ int   g_top[B_*NH*UMAX];
__device__ float g_vm [B_*NH*DH];
__device__ float g_upd[B_*NH*UMAX*DH];
__device__ float g_red[B_*DM];

// ---------------- threefry2x32 (JAX-compatible) ----------------
__host__ __device__ __forceinline__ void tf2x32(unsigned k0, unsigned k1,
                                                unsigned x0, unsigned x1,
                                                unsigned* o0, unsigned* o1) {
    unsigned ks[3] = {k0, k1, k0 ^ k1 ^ 0x1BD11BDAu};
    x0 += ks[0]; x1 += ks[1];
    const int R0[4] = {13,15,26,6};
    const int R1[4] = {17,29,16,24};
    #pragma unroll
    for (int g = 0; g < 5; g++) {
        #pragma unroll
        for (int q = 0; q < 4; q++) {
            int r = (g & 1) ? R1[q] : R0[q];
            x0 += x1;
            x1 = (x1 << r) | (x1 >> (32 - r));
            x1 ^= x0;
        }
        x0 += ks[(g + 1) % 3];
        x1 += ks[(g + 2) % 3] + (unsigned)(g + 1);
    }
    *o0 = x0; *o1 = x1;
}

__global__ void idx_kernel(int* __restrict__ idx, int L, int U, unsigned k0, unsigned k1) {
    int f = blockIdx.x * blockDim.x + threadIdx.x;
    if (f >= L * U) return;
    unsigned o0, o1;
    tf2x32(k0, k1, 0u, (unsigned)f, &o0, &o1);
    idx[f] = (int)((o0 ^ o1) % (unsigned)L);
}

// ---------------- token embedding + positional encoding ----------------
__global__ void embed_kernel(const float* __restrict__ xe, const float* __restrict__ tw,
                             float* __restrict__ out) {
    int i = blockIdx.x * blockDim.x + threadIdx.x;
    if (i >= B_ * SEQ * DM) return;
    int c = i % DM;
    int l = (i / DM) % SEQ;
    int b = i / (DM * SEQ);
    int lm = (l == 0) ? SEQ - 1 : l - 1;
    int lp = (l == SEQ - 1) ? 0 : l + 1;
    float v = tw[c*3+0]*xe[b*SEQ+lm] + tw[c*3+1]*xe[b*SEQ+l] + tw[c*3+2]*xe[b*SEQ+lp];
    int i2 = c >> 1;
    float div = expf((float)(2*i2) * (-9.210340371976184f / 512.0f));
    float arg = (float)l * div;
    v += (c & 1) ? cosf(arg) : sinf(arg);
    out[i] = v;
}

// ---------------- SGEMM 128x128 tile, 8x8 microtile, double-buffered ----------------
#define SST 132
__device__ __forceinline__ void gemm_body(
    const float* __restrict__ A, const float* __restrict__ W,
    const float* __restrict__ bias, float* __restrict__ C,
    int M, int N, int K, int act)
{
    __shared__ float As[2][16][SST];
    __shared__ float Ws[2][16][SST];
    int bm = blockIdx.y * 128, bn = blockIdx.x * 128;
    int tid = threadIdx.x;
    int tx = tid & 15, ty = tid >> 4;
    int lr = tid >> 2;
    int lc = (tid & 3) << 2;
    const float* pa0 = A + (size_t)(bm + lr) * K + lc;
    const float* pa1 = A + (size_t)(bm + lr + 64) * K + lc;
    const float* pw0 = W + (size_t)(bn + lr) * K + lc;
    const float* pw1 = W + (size_t)(bn + lr + 64) * K + lc;
    float acc[8][8] = {};
    {
        float4 a0 = *(const float4*)pa0;
        float4 a1 = *(const float4*)pa1;
        float4 w0 = *(const float4*)pw0;
        float4 w1 = *(const float4*)pw1;
        As[0][lc+0][lr]    = a0.x; As[0][lc+1][lr]    = a0.y; As[0][lc+2][lr]    = a0.z; As[0][lc+3][lr]    = a0.w;
        As[0][lc+0][lr+64] = a1.x; As[0][lc+1][lr+64] = a1.y; As[0][lc+2][lr+64] = a1.z; As[0][lc+3][lr+64] = a1.w;
        Ws[0][lc+0][lr]    = w0.x; Ws[0][lc+1][lr]    = w0.y; Ws[0][lc+2][lr]    = w0.z; Ws[0][lc+3][lr]    = w0.w;
        Ws[0][lc+0][lr+64] = w1.x; Ws[0][lc+1][lr+64] = w1.y; Ws[0][lc+2][lr+64] = w1.z; Ws[0][lc+3][lr+64] = w1.w;
    }
    __syncthreads();
    int buf = 0;
    for (int k0 = 0; k0 < K; k0 += 16) {
        float4 a0n, a1n, w0n, w1n;
        bool pf = (k0 + 16) < K;
        if (pf) {
            a0n = *(const float4*)(pa0 + k0 + 16);
            a1n = *(const float4*)(pa1 + k0 + 16);
            w0n = *(const float4*)(pw0 + k0 + 16);
            w1n = *(const float4*)(pw1 + k0 + 16);
        }
        #pragma unroll
        for (int kk = 0; kk < 16; kk++) {
            float a[8], w[8];
            *(float4*)(a)     = *(const float4*)&As[buf][kk][ty << 2];
            *(float4*)(a + 4) = *(const float4*)&As[buf][kk][64 + (ty << 2)];
            *(float4*)(w)     = *(const float4*)&Ws[buf][kk][tx << 2];
            *(float4*)(w + 4) = *(const float4*)&Ws[buf][kk][64 + (tx << 2)];
            #pragma unroll
            for (int i = 0; i < 8; i++)
                #pragma unroll
                for (int j = 0; j < 8; j++)
                    acc[i][j] += a[i] * w[j];
        }
        if (pf) {
            int nb = buf ^ 1;
            As[nb][lc+0][lr]    = a0n.x; As[nb][lc+1][lr]    = a0n.y; As[nb][lc+2][lr]    = a0n.z; As[nb][lc+3][lr]    = a0n.w;
            As[nb][lc+0][lr+64] = a1n.x; As[nb][lc+1][lr+64] = a1n.y; As[nb][lc+2][lr+64] = a1n.z; As[nb][lc+3][lr+64] = a1n.w;
            Ws[nb][lc+0][lr]    = w0n.x; Ws[nb][lc+1][lr]    = w0n.y; Ws[nb][lc+2][lr]    = w0n.z; Ws[nb][lc+3][lr]    = w0n.w;
            Ws[nb][lc+0][lr+64] = w1n.x; Ws[nb][lc+1][lr+64] = w1n.y; Ws[nb][lc+2][lr+64] = w1n.z; Ws[nb][lc+3][lr+64] = w1n.w;
        }
        __syncthreads();
        buf ^= 1;
    }
    #pragma unroll
    for (int i = 0; i < 8; i++) {
        int m = bm + ((i < 4) ? ((ty << 2) + i) : (64 + (ty << 2) + i - 4));
        #pragma unroll
        for (int jh = 0; jh < 2; jh++) {
            int n = bn + jh * 64 + (tx << 2);
            float4 o;
            o.x = acc[i][jh*4+0] + bias[n+0];
            o.y = acc[i][jh*4+1] + bias[n+1];
            o.z = acc[i][jh*4+2] + bias[n+2];
            o.w = acc[i][jh*4+3] + bias[n+3];
            if (act) {
                o.x = 0.5f * o.x * (1.0f + erff(o.x * 0.7071067811865475f));
                o.y = 0.5f * o.y * (1.0f + erff(o.y * 0.7071067811865475f));
                o.z = 0.5f * o.z * (1.0f + erff(o.z * 0.7071067811865475f));
                o.w = 0.5f * o.w * (1.0f + erff(o.w * 0.7071067811865475f));
            }
            *(float4*)(C + (size_t)m * N + n) = o;
        }
    }
}

__global__ __launch_bounds__(256, 2) void gemm_kernel(
    const float* __restrict__ A, const float* __restrict__ W,
    const float* __restrict__ bias, float* __restrict__ C,
    int M, int N, int K, int act)
{
    gemm_body(A, W, bias, C, M, N, K, act);
}

__global__ __launch_bounds__(256, 2) void qkv_kernel(
    const float* __restrict__ A,
    const float* __restrict__ Wq, const float* __restrict__ Wk, const float* __restrict__ Wv,
    const float* __restrict__ bq, const float* __restrict__ bk, const float* __restrict__ bv,
    float* __restrict__ q, float* __restrict__ k, float* __restrict__ v,
    int M, int K)
{
    const float* W; const float* b; float* C;
    if (blockIdx.z == 0)      { W = Wq; b = bq; C = q; }
    else if (blockIdx.z == 1) { W = Wk; b = bk; C = k; }
    else                      { W = Wv; b = bv; C = v; }
    gemm_body(A, W, b, C, M, DM, K, 0);
}

// ---------------- conv weight transpose: Wt[j][n][i] = Wc[n][i][j] ----------------
__global__ void wtrans_kernel(const float* __restrict__ Wc, float* __restrict__ Wt) {
    int i = blockIdx.x * blockDim.x + threadIdx.x;  // over DM*DM
    if (i >= DM * DM) return;
    float w0 = Wc[(size_t)i * 3 + 0];
    float w1 = Wc[(size_t)i * 3 + 1];
    float w2 = Wc[(size_t)i * 3 + 2];
    Wt[0 * DM * DM + i] = w0;
    Wt[1 * DM * DM + i] = w1;
    Wt[2 * DM * DM + i] = w2;
}

// ---------------- distil conv as GEMM (transposed weights) + BN-affine + ELU ----------------
__global__ __launch_bounds__(256, 2) void convgemm_kernel(
    const float* __restrict__ X, const float* __restrict__ Wt,
    const float* __restrict__ cb, const float* __restrict__ gg,
    const float* __restrict__ be, float* __restrict__ C, int L)
{
    __shared__ float As[2][16][SST];
    __shared__ float Ws[2][16][SST];
    int bm = blockIdx.y * 128, bn = blockIdx.x * 128;
    int tid = threadIdx.x;
    int tx = tid & 15, ty = tid >> 4;
    int lr = tid >> 2;
    int lc = (tid & 3) << 2;
    int m0 = bm + lr,      b0 = m0 / L, l0 = m0 % L;
    int m1 = bm + lr + 64, b1 = m1 / L, l1 = m1 % L;
    int n0 = bn + lr, n1 = bn + lr + 64;
    float acc[8][8] = {};

    auto loadk = [&](int k0, float4& a0, float4& a1, float4& w0, float4& w1) {
        int kk = k0 + lc;
        int j = kk / DM;
        int i0 = kk - j * DM;
        int ls0 = l0 - 1 + j; if (ls0 < 0) ls0 += L; else if (ls0 >= L) ls0 -= L;
        int ls1 = l1 - 1 + j; if (ls1 < 0) ls1 += L; else if (ls1 >= L) ls1 -= L;
        a0 = *(const float4*)(X + (size_t)(b0 * L + ls0) * DM + i0);
        a1 = *(const float4*)(X + (size_t)(b1 * L + ls1) * DM + i0);
        const float* wt = Wt + (size_t)j * DM * DM;
        w0 = *(const float4*)(wt + (size_t)n0 * DM + i0);
        w1 = *(const float4*)(wt + (size_t)n1 * DM + i0);
    };
    auto stores = [&](int nb, const float4& a0, const float4& a1,
                      const float4& w0, const float4& w1) {
        As[nb][lc+0][lr]    = a0.x; As[nb][lc+1][lr]    = a0.y; As[nb][lc+2][lr]    = a0.z; As[nb][lc+3][lr]    = a0.w;
        As[nb][lc+0][lr+64] = a1.x; As[nb][lc+1][lr+64] = a1.y; As[nb][lc+2][lr+64] = a1.z; As[nb][lc+3][lr+64] = a1.w;
        Ws[nb][lc+0][lr]    = w0.x; Ws[nb][lc+1][lr]    = w0.y; Ws[nb][lc+2][lr]    = w0.z; Ws[nb][lc+3][lr]    = w0.w;
        Ws[nb][lc+0][lr+64] = w1.x; Ws[nb][lc+1][lr+64] = w1.y; Ws[nb][lc+2][lr+64] = w1.z; Ws[nb][lc+3][lr+64] = w1.w;
    };

    {
        float4 a0, a1, w0, w1;
        loadk(0, a0, a1, w0, w1);
        stores(0, a0, a1, w0, w1);
    }
    __syncthreads();
    int buf = 0;
    for (int k0 = 0; k0 < 3 * DM; k0 += 16) {
        float4 a0n, a1n, w0n, w1n;
        bool pf = (k0 + 16) < 3 * DM;
        if (pf) loadk(k0 + 16, a0n, a1n, w0n, w1n);
        #pragma unroll
        for (int kk2 = 0; kk2 < 16; kk2++) {
            float a[8], w[8];
            *(float4*)(a)     = *(const float4*)&As[buf][kk2][ty << 2];
            *(float4*)(a + 4) = *(const float4*)&As[buf][kk2][64 + (ty << 2)];
            *(float4*)(w)     = *(const float4*)&Ws[buf][kk2][tx << 2];
            *(float4*)(w + 4) = *(const float4*)&Ws[buf][kk2][64 + (tx << 2)];
            #pragma unroll
            for (int i = 0; i < 8; i++)
                #pragma unroll
                for (int jj = 0; jj < 8; jj++)
                    acc[i][jj] += a[i] * w[jj];
        }
        if (pf) stores(buf ^ 1, a0n, a1n, w0n, w1n);
        __syncthreads();
        buf ^= 1;
    }
    const float invs = 0.9999950000374997f;
    #pragma unroll
    for (int i = 0; i < 8; i++) {
        int m = bm + ((i < 4) ? ((ty << 2) + i) : (64 + (ty << 2) + i - 4));
        #pragma unroll
        for (int jh = 0; jh < 2; jh++) {
            int n = bn + jh * 64 + (tx << 2);
            float4 o;
            float* po = &o.x;
            #pragma unroll
            for (int c4 = 0; c4 < 4; c4++) {
                float v = (acc[i][jh*4+c4] + cb[n+c4]) * invs * gg[n+c4] + be[n+c4];
                po[c4] = v > 0.0f ? v : expm1f(v);
            }
            *(float4*)(C + (size_t)m * DM + n) = o;
        }
    }
}

// maxpool kernel=3 stride=2 pad=1
__global__ void pool_kernel(const float* __restrict__ Y, float* __restrict__ X, int Lin) {
    int Lout = Lin >> 1;
    int i = blockIdx.x * blockDim.x + threadIdx.x;
    if (i >= B_ * Lout * DM) return;
    int c = i % DM;
    int lp = (i / DM) % Lout;
    int b = i / (DM * Lout);
    float mv = -INFINITY;
    #pragma unroll
    for (int j = 0; j < 3; j++) {
        int l = 2 * lp - 1 + j;
        if (l >= 0 && l < Lin) mv = fmaxf(mv, Y[(size_t)(b * Lin + l) * DM + c]);
    }
    X[(size_t)(b * Lout + lp) * DM + c] = mv;
}

// ---------------- sparsity measure: 2 queries/warp, 4-way u ILP ----------------
__global__ void m_kernel(const float* __restrict__ q, const float* __restrict__ k,
                         const int* __restrict__ idx, float* __restrict__ Mout,
                         int L, int U) {
    int gw = (blockIdx.x * blockDim.x + threadIdx.x) >> 5;
    int lane = threadIdx.x & 31;
    int half = lane >> 4;
    int lane4 = lane & 15;
    int qi = gw * 2 + half;
    if (qi >= B_ * NH * L) return;
    int l = qi % L;
    int bh = qi / L;
    int h = bh % NH, b = bh / NH;
    float4 q4 = ((const float4*)(q + (size_t)(b * L + l) * DM + h * DH))[lane4];
    const int* ip = idx + l * U;
    const float* kh = k + h * DH;
    float mx = -INFINITY, sum = 0.0f;
    int u = 0;
    for (; u + 4 <= U; u += 4) {
        int ki0 = ip[u], ki1 = ip[u+1], ki2 = ip[u+2], ki3 = ip[u+3];
        float4 k40 = ((const float4*)(kh + (size_t)(b * L + ki0) * DM))[lane4];
        float4 k41 = ((const float4*)(kh + (size_t)(b * L + ki1) * DM))[lane4];
        float4 k42 = ((const float4*)(kh + (size_t)(b * L + ki2) * DM))[lane4];
        float4 k43 = ((const float4*)(kh + (size_t)(b * L + ki3) * DM))[lane4];
        float p0 = q4.x*k40.x + q4.y*k40.y + q4.z*k40.z + q4.w*k40.w;
        float p1 = q4.x*k41.x + q4.y*k41.y + q4.z*k41.z + q4.w*k41.w;
        float p2 = q4.x*k42.x + q4.y*k42.y + q4.z*k42.z + q4.w*k42.w;
        float p3 = q4.x*k43.x + q4.y*k43.y + q4.z*k43.z + q4.w*k43.w;
        #pragma unroll
        for (int off = 8; off; off >>= 1) {
            p0 += __shfl_xor_sync(0xffffffffu, p0, off);
            p1 += __shfl_xor_sync(0xffffffffu, p1, off);
            p2 += __shfl_xor_sync(0xffffffffu, p2, off);
            p3 += __shfl_xor_sync(0xffffffffu, p3, off);
        }
        mx = fmaxf(mx, fmaxf(fmaxf(p0, p1), fmaxf(p2, p3)));
        sum += (p0 + p1) + (p2 + p3);
    }
    for (; u < U; u++) {
        int ki0 = ip[u];
        float4 k40 = ((const float4*)(kh + (size_t)(b * L + ki0) * DM))[lane4];
        float p0 = q4.x*k40.x + q4.y*k40.y + q4.z*k40.z + q4.w*k40.w;
        #pragma unroll
        for (int off = 8; off; off >>= 1) p0 += __shfl_xor_sync(0xffffffffu, p0, off);
        mx = fmaxf(mx, p0);
        sum += p0;
    }
    if (lane4 == 0) Mout[bh * L + l] = mx - sum / (float)U;
}

// ---------------- top-U selection ----------------
__global__ void topk_kernel(const float* __restrict__ Mv, int* __restrict__ top, int L, int U) {
    __shared__ float sm[2048];
    __shared__ float rv[256];
    __shared__ int   ri[256];
    int bh = blockIdx.x, tid = threadIdx.x;
    const float* row = Mv + bh * L;
    for (int l = tid; l < L; l += 256) sm[l] = row[l];
    __syncthreads();
    for (int it = 0; it < U; it++) {
        float bv = -INFINITY; int bi = 0x7fffffff;
        for (int l = tid; l < L; l += 256) {
            float v = sm[l];
            if (v > bv || (v == bv && l < bi)) { bv = v; bi = l; }
        }
        rv[tid] = bv; ri[tid] = bi;
        __syncthreads();
        for (int s = 128; s > 0; s >>= 1) {
            if (tid < s) {
                if (rv[tid+s] > rv[tid] || (rv[tid+s] == rv[tid] && ri[tid+s] < ri[tid])) {
                    rv[tid] = rv[tid+s]; ri[tid] = ri[tid+s];
                }
            }
            __syncthreads();
        }
        if (tid == 0) { top[bh * U + it] = ri[0]; sm[ri[0]] = -INFINITY; }
        __syncthreads();
    }
}

__global__ void vmean_kernel(const float* __restrict__ v, float* __restrict__ vm, int L) {
    __shared__ float sred[256];
    int bh = blockIdx.x;
    int h = bh % NH, b = bh / NH;
    int tid = threadIdx.x;
    int d = tid & 63, part = tid >> 6;
    int chunk = L >> 2;
    float acc = 0.0f;
    for (int l = part * chunk; l < (part + 1) * chunk; l++)
        acc += v[(size_t)(b * L + l) * DM + h * DH + d];
    sred[tid] = acc;
    __syncthreads();
    if (tid < 128) sred[tid] += sred[tid + 128];
    __syncthreads();
    if (tid < 64) vm[bh * DH + tid] = (sred[tid] + sred[tid + 64]) / (float)L;
}

// ---------------- softmax attention, UB queries per block (K/V reuse) ----------------
__global__ void attn_kernel(const float* __restrict__ q, const float* __restrict__ k,
                            const float* __restrict__ v, const int* __restrict__ top,
                            float* __restrict__ upd, int L, int U, int nub) {
    __shared__ float qs[UB][64];
    __shared__ float s[UB][2048];
    __shared__ float red[UB][128];
    int blk = blockIdx.x;
    int ub = blk % nub;
    int bh = blk / nub;
    int h = bh % NH, b = bh / NH;
    int tid = threadIdx.x; // 128
    int u0 = ub * UB;
    int nq = U - u0; if (nq > UB) nq = UB;

    for (int t = tid; t < UB * 64; t += 128) {
        int qq = t >> 6, d = t & 63;
        float val = 0.0f;
        if (qq < nq) {
            int lq = top[bh * U + u0 + qq];
            val = q[(size_t)(b * L + lq) * DM + h * DH + d];
        }
        qs[qq][d] = val;
    }
    __syncthreads();

    float lmax[UB];
    #pragma unroll
    for (int qq = 0; qq < UB; qq++) lmax[qq] = -INFINITY;
    for (int l = tid; l < L; l += 128) {
        const float4* kp4 = (const float4*)(k + (size_t)(b * L + l) * DM + h * DH);
        float acc[UB] = {};
        #pragma unroll
        for (int d4 = 0; d4 < 16; d4++) {
            float4 kk = kp4[d4];
            #pragma unroll
            for (int qq = 0; qq < UB; qq++) {
                float4 qv = ((const float4*)qs[qq])[d4];
                acc[qq] += qv.x*kk.x + qv.y*kk.y + qv.z*kk.z + qv.w*kk.w;
            }
        }
        #pragma unroll
        for (int qq = 0; qq < UB; qq++) {
            float a = acc[qq] * 0.125f;
            s[qq][l] = a;
            lmax[qq] = fmaxf(lmax[qq], a);
        }
    }
    #pragma unroll
    for (int qq = 0; qq < UB; qq++) red[qq][tid] = lmax[qq];
    __syncthreads();
    for (int st = 64; st; st >>= 1) {
        if (tid < st) {
            #pragma unroll
            for (int qq = 0; qq < UB; qq++)
                red[qq][tid] = fmaxf(red[qq][tid], red[qq][tid + st]);
        }
        __syncthreads();
    }
    float mx[UB];
    #pragma unroll
    for (int qq = 0; qq < UB; qq++) mx[qq] = red[qq][0];
    __syncthreads();

    float lsum[UB] = {};
    for (int l = tid; l < L; l += 128) {
        #pragma unroll
        for (int qq = 0; qq < UB; qq++) {
            float e = expf(s[qq][l] - mx[qq]);
            s[qq][l] = e;
            lsum[qq] += e;
        }
    }
    #pragma unroll
    for (int qq = 0; qq < UB; qq++) red[qq][tid] = lsum[qq];
    __syncthreads();
    for (int st = 64; st; st >>= 1) {
        if (tid < st) {
            #pragma unroll
            for (int qq = 0; qq < UB; qq++)
                red[qq][tid] += red[qq][tid + st];
        }
        __syncthreads();
    }
    float inv[UB];
    #pragma unroll
    for (int qq = 0; qq < UB; qq++) inv[qq] = 1.0f / red[qq][0];
    __syncthreads();

    int d = tid & 63, halfid = tid >> 6;
    int l0 = halfid * (L >> 1), l1 = l0 + (L >> 1);
    float acc[UB] = {};
    for (int l = l0; l < l1; l++) {
        float vv = v[(size_t)(b * L + l) * DM + h * DH + d];
        #pragma unroll
        for (int qq = 0; qq < UB; qq++) acc[qq] += s[qq][l] * vv;
    }
    #pragma unroll
    for (int qq = 0; qq < UB; qq++) red[qq][tid] = acc[qq];
    __syncthreads();
    if (tid < 64) {
        for (int qq = 0; qq < nq; qq++)
            upd[(size_t)(bh * U + u0 + qq) * DH + tid] =
                (red[qq][tid] + red[qq][tid + 64]) * inv[qq];
    }
}

__global__ void oinit_kernel(float* __restrict__ o, const float* __restrict__ vm, int L) {
    int i = blockIdx.x * blockDim.x + threadIdx.x;
    if (i >= B_ * L * DM) return;
    int c = i % DM;
    int b = i / (DM * L);
    o[i] = vm[(b * NH + (c >> 6)) * DH + (c & 63)];
}

__global__ void scatter_kernel(float* __restrict__ o, const float* __restrict__ upd,
                               const int* __restrict__ top, int L, int U) {
    int bhu = blockIdx.x, d = threadIdx.x;
    int u = bhu % U;
    int bh = bhu / U;
    int h = bh % NH, b = bh / NH;
    int l = top[bh * U + u];
    o[(size_t)(b * L + l) * DM + h * DH + d] = upd[(size_t)(bh * U + u) * DH + d];
}

// ---------------- x = LayerNorm(x + t) ----------------
__global__ void addln_kernel(float* __restrict__ x, const float* __restrict__ t,
                             const float* __restrict__ g, const float* __restrict__ bb) {
    __shared__ float row[512];
    __shared__ float red[256];
    size_t r = blockIdx.x;
    int tid = threadIdx.x;
    float v0 = x[r * 512 + tid]       + (t ? t[r * 512 + tid]       : 0.0f);
    float v1 = x[r * 512 + tid + 256] + (t ? t[r * 512 + tid + 256] : 0.0f);
    row[tid] = v0; row[tid + 256] = v1;
    red[tid] = v0 + v1;
    __syncthreads();
    for (int s = 128; s; s >>= 1) { if (tid < s) red[tid] += red[tid + s]; __syncthreads(); }
    float mu = red[0] * (1.0f / 512.0f);
    __syncthreads();
    float d0 = row[tid] - mu, d1 = row[tid + 256] - mu;
    red[tid] = d0 * d0 + d1 * d1;
    __syncthreads();
    for (int s = 128; s; s >>= 1) { if (tid < s) red[tid] += red[tid + s]; __syncthreads(); }
    float rstd = rsqrtf(red[0] * (1.0f / 512.0f) + LNEPS);
    x[r * 512 + tid]       = d0 * rstd * g[tid]       + bb[tid];
    x[r * 512 + tid + 256] = d1 * rstd * g[tid + 256] + bb[tid + 256];
}

__global__ void rowmax_kernel(const float* __restrict__ x, float* __restrict__ outr, int L) {
    int b = blockIdx.x, c = threadIdx.x;
    float m = -INFINITY;
    for (int l = 0; l < L; l++) m = fmaxf(m, x[(size_t)(b * L + l) * DM + c]);
    outr[b * DM + c] = m;
}

__global__ void proj_kernel(const float* __restrict__ red, const float* __restrict__ pw,
                            const float* __restrict__ pb, float* __restrict__ out) {
    int w = threadIdx.x >> 5, lane = threadIdx.x & 31;
    int b = w >> 1, o = w & 1;
    float acc = 0.0f;
    for (int c = lane; c < DM; c += 32) acc += red[b * DM + c] * pw[o * DM + c];
    #pragma unroll
    for (int s = 16; s; s >>= 1) acc += __shfl_xor_sync(0xffffffffu, acc, s);
    if (lane == 0) out[b * 2 + o] = acc + pb[o];
}

// ---------------- host ----------------
extern "C" void kernel_launch(void* const* d_in, const int* in_sizes, int n_in,
                              void* d_out, int out_size) {
    (void)n_in; (void)out_size;
    const float* x_enc = (const float*)d_in[0];
    const float* tok_w = (const float*)d_in[1];
    const float *Wq, *Wk, *Wv, *Wo, *bq, *bk, *bv, *bo;
    if (in_sizes[5] > 10000) {
        Wq = (const float*)d_in[2]; Wk = (const float*)d_in[3];
        Wv = (const float*)d_in[4]; Wo = (const float*)d_in[5];
        bq = (const float*)d_in[6]; bk = (const float*)d_in[7];
        bv = (const float*)d_in[8]; bo = (const float*)d_in[9];
    } else {
        Wq = (const float*)d_in[2]; Wk = (const float*)d_in[3];
        Wv = (const float*)d_in[4]; bq = (const float*)d_in[5];
        bk = (const float*)d_in[6]; bv = (const float*)d_in[7];
        Wo = (const float*)d_in[8]; bo = (const float*)d_in[9];
    }
    const float* W1   = (const float*)d_in[10];
    const float* b1   = (const float*)d_in[11];
    const float* W2   = (const float*)d_in[12];
    const float* b2   = (const float*)d_in[13];
    const float* ln1g = (const float*)d_in[14];
    const float* ln1b = (const float*)d_in[15];
    const float* ln2g = (const float*)d_in[16];
    const float* ln2b = (const float*)d_in[17];
    const float* dcw  = (const float*)d_in[18];
    const float* dcb  = (const float*)d_in[19];
    const float* bng  = (const float*)d_in[20];
    const float* bnb  = (const float*)d_in[21];
    const float* lnfg = (const float*)d_in[22];
    const float* lnfb = (const float*)d_in[23];
    const float* pw   = (const float*)d_in[24];
    const float* pb   = (const float*)d_in[25];

    float *x, *q, *k, *v, *o, *t1, *t2, *Mb, *vm, *upd, *redb;
    int *idxb, *topb;
    cudaGetSymbolAddress((void**)&x,    g_x);
    cudaGetSymbolAddress((void**)&q,    g_q);
    cudaGetSymbolAddress((void**)&k,    g_k);
    cudaGetSymbolAddress((void**)&v,    g_v);
    cudaGetSymbolAddress((void**)&o,    g_o);
    cudaGetSymbolAddress((void**)&t1,   g_t1);
    cudaGetSymbolAddress((void**)&t2,   g_t2);
    cudaGetSymbolAddress((void**)&Mb,   g_M);
    cudaGetSymbolAddress((void**)&vm,   g_vm);
    cudaGetSymbolAddress((void**)&upd,  g_upd);
    cudaGetSymbolAddress((void**)&redb, g_red);
    cudaGetSymbolAddress((void**)&idxb, g_idx);
    cudaGetSymbolAddress((void**)&topb, g_top);

    embed_kernel<<<(B_*SEQ*DM + 255) / 256, 256>>>(x_enc, tok_w, x);

    int L = SEQ;
    for (int i = 0; i < NL; i++) {
        int Mrows = B_ * L;
        dim3 gg(DM / 128, Mrows / 128);
        dim3 g3(DM / 128, Mrows / 128, 3);
        qkv_kernel<<<g3, 256>>>(x, Wq + i*DM*DM, Wk + i*DM*DM, Wv + i*DM*DM,
                                bq + i*DM, bk + i*DM, bv + i*DM,
                                q, k, v, Mrows, DM);

        int U = 5 * (int)ceil(log((double)L));
        if (U > L) U = L;

        unsigned f0, f1, c0, c1;
        tf2x32(0u, 42u, 0u, (unsigned)i, &f0, &f1);
        tf2x32(f0, f1, 0u, 1u, &c0, &c1);

        idx_kernel<<<(L*U + 255) / 256, 256>>>(idxb, L, U, c0, c1);
        m_kernel<<<(B_*NH*L/2*32 + 127) / 128, 128>>>(q, k, idxb, Mb, L, U);
        topk_kernel<<<B_*NH, 256>>>(Mb, topb, L, U);
        vmean_kernel<<<B_*NH, 256>>>(v, vm, L);
        int nub = (U + UB - 1) / UB;
        attn_kernel<<<B_*NH*nub, 128>>>(q, k, v, topb, upd, L, U, nub);
        oinit_kernel<<<(B_*L*DM + 255) / 256, 256>>>(o, vm, L);
        scatter_kernel<<<B_*NH*U, 64>>>(o, upd, topb, L, U);

        gemm_kernel<<<gg, 256>>>(o, Wo + i*DM*DM, bo + i*DM, t1, Mrows, DM, DM, 0);
        addln_kernel<<<Mrows, 256>>>(x, t1, ln1g + i*DM, ln1b + i*DM);
        gemm_kernel<<<gg, 256>>>(x, W1 + i*DM*DM, b1 + i*DM, t1, Mrows, DM, DM, 1);
        gemm_kernel<<<gg, 256>>>(t1, W2 + i*DM*DM, b2 + i*DM, t2, Mrows, DM, DM, 0);
        addln_kernel<<<Mrows, 256>>>(x, t2, ln2g + i*DM, ln2b + i*DM);

        if (i < NL - 1) {
            // transpose conv weights into t2 (free at this point), then conv
            wtrans_kernel<<<(DM*DM + 255) / 256, 256>>>(dcw + (size_t)i*DM*DM*3, t2);
            convgemm_kernel<<<gg, 256>>>(x, t2, dcb + i*DM,
                                         bng + i*DM, bnb + i*DM, t1, L);
            int Lout = L / 2;
            pool_kernel<<<(B_*Lout*DM + 255) / 256, 256>>>(t1, x, L);
            L = Lout;
        }
    }

    addln_kernel<<<B_*L, 256>>>(x, (const float*)nullptr, lnfg, lnfb);
    rowmax_kernel<<<B_, 512>>>(x, redb, L);
    proj_kernel<<<1, 512>>>(redb, pw, pb, (float*)d_out);
}

// round 14
// speedup vs baseline: 1.4207x; 1.1253x over previous
#include <cuda_runtime.h>
#include <math.h>

#define B_ 8
#define SEQ 2048
#define DM 512
#define NH 8
#define DH 64
#define NL 3
#define UMAX 40
#define UB 8
#define LNEPS 1e-5f

// ---------------- scratch ----------------
__device__ float g_x [B_*SEQ*DM];
__device__ float g_q [B_*SEQ*DM];
__device__ float g_k [B_*SEQ*DM];
__device__ float g_v [B_*SEQ*DM];
__device__ float g_t1[B_*SEQ*DM];
__device__ float g_t2[B_*SEQ*DM];   // also reused as transposed conv weights (3*DM*DM floats)
__device__ float g_M [B_*NH*SEQ];
__device__ int   g_idx[SEQ*UMAX];
__device__ int   g_top[B_*NH*UMAX];
__device__ float g_vm [B_*NH*DH];
__device__ float g_upd[B_*NH*UMAX*DH];
__device__ float g_red[B_*DM];
__device__ float g_base[B_*DM];

// ---------------- threefry2x32 (JAX-compatible) ----------------
__host__ __device__ __forceinline__ void tf2x32(unsigned k0, unsigned k1,
                                                unsigned x0, unsigned x1,
                                                unsigned* o0, unsigned* o1) {
    unsigned ks[3] = {k0, k1, k0 ^ k1 ^ 0x1BD11BDAu};
    x0 += ks[0]; x1 += ks[1];
    const int R0[4] = {13,15,26,6};
    const int R1[4] = {17,29,16,24};
    #pragma unroll
    for (int g = 0; g < 5; g++) {
        #pragma unroll
        for (int q = 0; q < 4; q++) {
            int r = (g & 1) ? R1[q] : R0[q];
            x0 += x1;
            x1 = (x1 << r) | (x1 >> (32 - r));
            x1 ^= x0;
        }
        x0 += ks[(g + 1) % 3];
        x1 += ks[(g + 2) % 3] + (unsigned)(g + 1);
    }
    *o0 = x0; *o1 = x1;
}

__global__ void idx_kernel(int* __restrict__ idx, int L, int U, unsigned k0, unsigned k1) {
    int f = blockIdx.x * blockDim.x + threadIdx.x;
    if (f >= L * U) return;
    unsigned o0, o1;
    tf2x32(k0, k1, 0u, (unsigned)f, &o0, &o1);
    idx[f] = (int)((o0 ^ o1) % (unsigned)L);
}

// ---------------- token embedding + positional encoding ----------------
__global__ void embed_kernel(const float* __restrict__ xe, const float* __restrict__ tw,
                             float* __restrict__ out) {
    int i = blockIdx.x * blockDim.x + threadIdx.x;
    if (i >= B_ * SEQ * DM) return;
    int c = i % DM;
    int l = (i / DM) % SEQ;
    int b = i / (DM * SEQ);
    int lm = (l == 0) ? SEQ - 1 : l - 1;
    int lp = (l == SEQ - 1) ? 0 : l + 1;
    float v = tw[c*3+0]*xe[b*SEQ+lm] + tw[c*3+1]*xe[b*SEQ+l] + tw[c*3+2]*xe[b*SEQ+lp];
    int i2 = c >> 1;
    float div = expf((float)(2*i2) * (-9.210340371976184f / 512.0f));
    float arg = (float)l * div;
    v += (c & 1) ? cosf(arg) : sinf(arg);
    out[i] = v;
}

// ---------------- SGEMM 128x128 tile, 8x8 microtile, double-buffered ----------------
#define SST 132
__device__ __forceinline__ void gemm_body(
    const float* __restrict__ A, const float* __restrict__ W,
    const float* __restrict__ bias, float* __restrict__ C,
    int M, int N, int K, int act)
{
    __shared__ float As[2][16][SST];
    __shared__ float Ws[2][16][SST];
    int bm = blockIdx.y * 128, bn = blockIdx.x * 128;
    int tid = threadIdx.x;
    int tx = tid & 15, ty = tid >> 4;
    int lr = tid >> 2;
    int lc = (tid & 3) << 2;
    const float* pa0 = A + (size_t)(bm + lr) * K + lc;
    const float* pa1 = A + (size_t)(bm + lr + 64) * K + lc;
    const float* pw0 = W + (size_t)(bn + lr) * K + lc;
    const float* pw1 = W + (size_t)(bn + lr + 64) * K + lc;
    float acc[8][8] = {};
    {
        float4 a0 = *(const float4*)pa0;
        float4 a1 = *(const float4*)pa1;
        float4 w0 = *(const float4*)pw0;
        float4 w1 = *(const float4*)pw1;
        As[0][lc+0][lr]    = a0.x; As[0][lc+1][lr]    = a0.y; As[0][lc+2][lr]    = a0.z; As[0][lc+3][lr]    = a0.w;
        As[0][lc+0][lr+64] = a1.x; As[0][lc+1][lr+64] = a1.y; As[0][lc+2][lr+64] = a1.z; As[0][lc+3][lr+64] = a1.w;
        Ws[0][lc+0][lr]    = w0.x; Ws[0][lc+1][lr]    = w0.y; Ws[0][lc+2][lr]    = w0.z; Ws[0][lc+3][lr]    = w0.w;
        Ws[0][lc+0][lr+64] = w1.x; Ws[0][lc+1][lr+64] = w1.y; Ws[0][lc+2][lr+64] = w1.z; Ws[0][lc+3][lr+64] = w1.w;
    }
    __syncthreads();
    int buf = 0;
    for (int k0 = 0; k0 < K; k0 += 16) {
        float4 a0n, a1n, w0n, w1n;
        bool pf = (k0 + 16) < K;
        if (pf) {
            a0n = *(const float4*)(pa0 + k0 + 16);
            a1n = *(const float4*)(pa1 + k0 + 16);
            w0n = *(const float4*)(pw0 + k0 + 16);
            w1n = *(const float4*)(pw1 + k0 + 16);
        }
        #pragma unroll
        for (int kk = 0; kk < 16; kk++) {
            float a[8], w[8];
            *(float4*)(a)     = *(const float4*)&As[buf][kk][ty << 2];
            *(float4*)(a + 4) = *(const float4*)&As[buf][kk][64 + (ty << 2)];
            *(float4*)(w)     = *(const float4*)&Ws[buf][kk][tx << 2];
            *(float4*)(w + 4) = *(const float4*)&Ws[buf][kk][64 + (tx << 2)];
            #pragma unroll
            for (int i = 0; i < 8; i++)
                #pragma unroll
                for (int j = 0; j < 8; j++)
                    acc[i][j] += a[i] * w[j];
        }
        if (pf) {
            int nb = buf ^ 1;
            As[nb][lc+0][lr]    = a0n.x; As[nb][lc+1][lr]    = a0n.y; As[nb][lc+2][lr]    = a0n.z; As[nb][lc+3][lr]    = a0n.w;
            As[nb][lc+0][lr+64] = a1n.x; As[nb][lc+1][lr+64] = a1n.y; As[nb][lc+2][lr+64] = a1n.z; As[nb][lc+3][lr+64] = a1n.w;
            Ws[nb][lc+0][lr]    = w0n.x; Ws[nb][lc+1][lr]    = w0n.y; Ws[nb][lc+2][lr]    = w0n.z; Ws[nb][lc+3][lr]    = w0n.w;
            Ws[nb][lc+0][lr+64] = w1n.x; Ws[nb][lc+1][lr+64] = w1n.y; Ws[nb][lc+2][lr+64] = w1n.z; Ws[nb][lc+3][lr+64] = w1n.w;
        }
        __syncthreads();
        buf ^= 1;
    }
    #pragma unroll
    for (int i = 0; i < 8; i++) {
        int m = bm + ((i < 4) ? ((ty << 2) + i) : (64 + (ty << 2) + i - 4));
        #pragma unroll
        for (int jh = 0; jh < 2; jh++) {
            int n = bn + jh * 64 + (tx << 2);
            float4 o;
            o.x = acc[i][jh*4+0] + bias[n+0];
            o.y = acc[i][jh*4+1] + bias[n+1];
            o.z = acc[i][jh*4+2] + bias[n+2];
            o.w = acc[i][jh*4+3] + bias[n+3];
            if (act) {
                o.x = 0.5f * o.x * (1.0f + erff(o.x * 0.7071067811865475f));
                o.y = 0.5f * o.y * (1.0f + erff(o.y * 0.7071067811865475f));
                o.z = 0.5f * o.z * (1.0f + erff(o.z * 0.7071067811865475f));
                o.w = 0.5f * o.w * (1.0f + erff(o.w * 0.7071067811865475f));
            }
            *(float4*)(C + (size_t)m * N + n) = o;
        }
    }
}

__global__ __launch_bounds__(256, 2) void gemm_kernel(
    const float* __restrict__ A, const float* __restrict__ W,
    const float* __restrict__ bias, float* __restrict__ C,
    int M, int N, int K, int act)
{
    gemm_body(A, W, bias, C, M, N, K, act);
}

__global__ __launch_bounds__(256, 2) void qkv_kernel(
    const float* __restrict__ A,
    const float* __restrict__ Wq, const float* __restrict__ Wk, const float* __restrict__ Wv,
    const float* __restrict__ bq, const float* __restrict__ bk, const float* __restrict__ bv,
    float* __restrict__ q, float* __restrict__ k, float* __restrict__ v,
    int M, int K)
{
    const float* W; const float* b; float* C;
    if (blockIdx.z == 0)      { W = Wq; b = bq; C = q; }
    else if (blockIdx.z == 1) { W = Wk; b = bk; C = k; }
    else                      { W = Wv; b = bv; C = v; }
    gemm_body(A, W, b, C, M, DM, K, 0);
}

// ---------------- conv weight transpose: Wt[j][n][i] = Wc[n][i][j] ----------------
__global__ void wtrans_kernel(const float* __restrict__ Wc, float* __restrict__ Wt) {
    int i = blockIdx.x * blockDim.x + threadIdx.x;
    if (i >= DM * DM) return;
    float w0 = Wc[(size_t)i * 3 + 0];
    float w1 = Wc[(size_t)i * 3 + 1];
    float w2 = Wc[(size_t)i * 3 + 2];
    Wt[0 * DM * DM + i] = w0;
    Wt[1 * DM * DM + i] = w1;
    Wt[2 * DM * DM + i] = w2;
}

// ---------------- distil conv as GEMM (transposed weights) + BN-affine + ELU ----------------
__global__ __launch_bounds__(256, 2) void convgemm_kernel(
    const float* __restrict__ X, const float* __restrict__ Wt,
    const float* __restrict__ cb, const float* __restrict__ gg,
    const float* __restrict__ be, float* __restrict__ C, int L)
{
    __shared__ float As[2][16][SST];
    __shared__ float Ws[2][16][SST];
    int bm = blockIdx.y * 128, bn = blockIdx.x * 128;
    int tid = threadIdx.x;
    int tx = tid & 15, ty = tid >> 4;
    int lr = tid >> 2;
    int lc = (tid & 3) << 2;
    int m0 = bm + lr,      b0 = m0 / L, l0 = m0 % L;
    int m1 = bm + lr + 64, b1 = m1 / L, l1 = m1 % L;
    int n0 = bn + lr, n1 = bn + lr + 64;
    float acc[8][8] = {};

    auto loadk = [&](int k0, float4& a0, float4& a1, float4& w0, float4& w1) {
        int kk = k0 + lc;
        int j = kk / DM;
        int i0 = kk - j * DM;
        int ls0 = l0 - 1 + j; if (ls0 < 0) ls0 += L; else if (ls0 >= L) ls0 -= L;
        int ls1 = l1 - 1 + j; if (ls1 < 0) ls1 += L; else if (ls1 >= L) ls1 -= L;
        a0 = *(const float4*)(X + (size_t)(b0 * L + ls0) * DM + i0);
        a1 = *(const float4*)(X + (size_t)(b1 * L + ls1) * DM + i0);
        const float* wt = Wt + (size_t)j * DM * DM;
        w0 = *(const float4*)(wt + (size_t)n0 * DM + i0);
        w1 = *(const float4*)(wt + (size_t)n1 * DM + i0);
    };
    auto stores = [&](int nb, const float4& a0, const float4& a1,
                      const float4& w0, const float4& w1) {
        As[nb][lc+0][lr]    = a0.x; As[nb][lc+1][lr]    = a0.y; As[nb][lc+2][lr]    = a0.z; As[nb][lc+3][lr]    = a0.w;
        As[nb][lc+0][lr+64] = a1.x; As[nb][lc+1][lr+64] = a1.y; As[nb][lc+2][lr+64] = a1.z; As[nb][lc+3][lr+64] = a1.w;
        Ws[nb][lc+0][lr]    = w0.x; Ws[nb][lc+1][lr]    = w0.y; Ws[nb][lc+2][lr]    = w0.z; Ws[nb][lc+3][lr]    = w0.w;
        Ws[nb][lc+0][lr+64] = w1.x; Ws[nb][lc+1][lr+64] = w1.y; Ws[nb][lc+2][lr+64] = w1.z; Ws[nb][lc+3][lr+64] = w1.w;
    };

    {
        float4 a0, a1, w0, w1;
        loadk(0, a0, a1, w0, w1);
        stores(0, a0, a1, w0, w1);
    }
    __syncthreads();
    int buf = 0;
    for (int k0 = 0; k0 < 3 * DM; k0 += 16) {
        float4 a0n, a1n, w0n, w1n;
        bool pf = (k0 + 16) < 3 * DM;
        if (pf) loadk(k0 + 16, a0n, a1n, w0n, w1n);
        #pragma unroll
        for (int kk2 = 0; kk2 < 16; kk2++) {
            float a[8], w[8];
            *(float4*)(a)     = *(const float4*)&As[buf][kk2][ty << 2];
            *(float4*)(a + 4) = *(const float4*)&As[buf][kk2][64 + (ty << 2)];
            *(float4*)(w)     = *(const float4*)&Ws[buf][kk2][tx << 2];
            *(float4*)(w + 4) = *(const float4*)&Ws[buf][kk2][64 + (tx << 2)];
            #pragma unroll
            for (int i = 0; i < 8; i++)
                #pragma unroll
                for (int jj = 0; jj < 8; jj++)
                    acc[i][jj] += a[i] * w[jj];
        }
        if (pf) stores(buf ^ 1, a0n, a1n, w0n, w1n);
        __syncthreads();
        buf ^= 1;
    }
    const float invs = 0.9999950000374997f;
    #pragma unroll
    for (int i = 0; i < 8; i++) {
        int m = bm + ((i < 4) ? ((ty << 2) + i) : (64 + (ty << 2) + i - 4));
        #pragma unroll
        for (int jh = 0; jh < 2; jh++) {
            int n = bn + jh * 64 + (tx << 2);
            float4 o;
            float* po = &o.x;
            #pragma unroll
            for (int c4 = 0; c4 < 4; c4++) {
                float v = (acc[i][jh*4+c4] + cb[n+c4]) * invs * gg[n+c4] + be[n+c4];
                po[c4] = v > 0.0f ? v : expm1f(v);
            }
            *(float4*)(C + (size_t)m * DM + n) = o;
        }
    }
}

// maxpool kernel=3 stride=2 pad=1
__global__ void pool_kernel(const float* __restrict__ Y, float* __restrict__ X, int Lin) {
    int Lout = Lin >> 1;
    int i = blockIdx.x * blockDim.x + threadIdx.x;
    if (i >= B_ * Lout * DM) return;
    int c = i % DM;
    int lp = (i / DM) % Lout;
    int b = i / (DM * Lout);
    float mv = -INFINITY;
    #pragma unroll
    for (int j = 0; j < 3; j++) {
        int l = 2 * lp - 1 + j;
        if (l >= 0 && l < Lin) mv = fmaxf(mv, Y[(size_t)(b * Lin + l) * DM + c]);
    }
    X[(size_t)(b * Lout + lp) * DM + c] = mv;
}

// ---------------- sparsity measure: 2 queries/warp, 4-way u ILP ----------------
__global__ void m_kernel(const float* __restrict__ q, const float* __restrict__ k,
                         const int* __restrict__ idx, float* __restrict__ Mout,
                         int L, int U) {
    int gw = (blockIdx.x * blockDim.x + threadIdx.x) >> 5;
    int lane = threadIdx.x & 31;
    int half = lane >> 4;
    int lane4 = lane & 15;
    int qi = gw * 2 + half;
    if (qi >= B_ * NH * L) return;
    int l = qi % L;
    int bh = qi / L;
    int h = bh % NH, b = bh / NH;
    float4 q4 = ((const float4*)(q + (size_t)(b * L + l) * DM + h * DH))[lane4];
    const int* ip = idx + l * U;
    const float* kh = k + h * DH;
    float mx = -INFINITY, sum = 0.0f;
    int u = 0;
    for (; u + 4 <= U; u += 4) {
        int ki0 = ip[u], ki1 = ip[u+1], ki2 = ip[u+2], ki3 = ip[u+3];
        float4 k40 = ((const float4*)(kh + (size_t)(b * L + ki0) * DM))[lane4];
        float4 k41 = ((const float4*)(kh + (size_t)(b * L + ki1) * DM))[lane4];
        float4 k42 = ((const float4*)(kh + (size_t)(b * L + ki2) * DM))[lane4];
        float4 k43 = ((const float4*)(kh + (size_t)(b * L + ki3) * DM))[lane4];
        float p0 = q4.x*k40.x + q4.y*k40.y + q4.z*k40.z + q4.w*k40.w;
        float p1 = q4.x*k41.x + q4.y*k41.y + q4.z*k41.z + q4.w*k41.w;
        float p2 = q4.x*k42.x + q4.y*k42.y + q4.z*k42.z + q4.w*k42.w;
        float p3 = q4.x*k43.x + q4.y*k43.y + q4.z*k43.z + q4.w*k43.w;
        #pragma unroll
        for (int off = 8; off; off >>= 1) {
            p0 += __shfl_xor_sync(0xffffffffu, p0, off);
            p1 += __shfl_xor_sync(0xffffffffu, p1, off);
            p2 += __shfl_xor_sync(0xffffffffu, p2, off);
            p3 += __shfl_xor_sync(0xffffffffu, p3, off);
        }
        mx = fmaxf(mx, fmaxf(fmaxf(p0, p1), fmaxf(p2, p3)));
        sum += (p0 + p1) + (p2 + p3);
    }
    for (; u < U; u++) {
        int ki0 = ip[u];
        float4 k40 = ((const float4*)(kh + (size_t)(b * L + ki0) * DM))[lane4];
        float p0 = q4.x*k40.x + q4.y*k40.y + q4.z*k40.z + q4.w*k40.w;
        #pragma unroll
        for (int off = 8; off; off >>= 1) p0 += __shfl_xor_sync(0xffffffffu, p0, off);
        mx = fmaxf(mx, p0);
        sum += p0;
    }
    if (lane4 == 0) Mout[bh * L + l] = mx - sum / (float)U;
}

// ---------------- top-U selection ----------------
__global__ void topk_kernel(const float* __restrict__ Mv, int* __restrict__ top, int L, int U) {
    __shared__ float sm[2048];
    __shared__ float rv[256];
    __shared__ int   ri[256];
    int bh = blockIdx.x, tid = threadIdx.x;
    const float* row = Mv + bh * L;
    for (int l = tid; l < L; l += 256) sm[l] = row[l];
    __syncthreads();
    for (int it = 0; it < U; it++) {
        float bv = -INFINITY; int bi = 0x7fffffff;
        for (int l = tid; l < L; l += 256) {
            float v = sm[l];
            if (v > bv || (v == bv && l < bi)) { bv = v; bi = l; }
        }
        rv[tid] = bv; ri[tid] = bi;
        __syncthreads();
        for (int s = 128; s > 0; s >>= 1) {
            if (tid < s) {
                if (rv[tid+s] > rv[tid] || (rv[tid+s] == rv[tid] && ri[tid+s] < ri[tid])) {
                    rv[tid] = rv[tid+s]; ri[tid] = ri[tid+s];
                }
            }
            __syncthreads();
        }
        if (tid == 0) { top[bh * U + it] = ri[0]; sm[ri[0]] = -INFINITY; }
        __syncthreads();
    }
}

__global__ void vmean_kernel(const float* __restrict__ v, float* __restrict__ vm, int L) {
    __shared__ float sred[256];
    int bh = blockIdx.x;
    int h = bh % NH, b = bh / NH;
    int tid = threadIdx.x;
    int d = tid & 63, part = tid >> 6;
    int chunk = L >> 2;
    float acc = 0.0f;
    for (int l = part * chunk; l < (part + 1) * chunk; l++)
        acc += v[(size_t)(b * L + l) * DM + h * DH + d];
    sred[tid] = acc;
    __syncthreads();
    if (tid < 128) sred[tid] += sred[tid + 128];
    __syncthreads();
    if (tid < 64) vm[bh * DH + tid] = (sred[tid] + sred[tid + 64]) / (float)L;
}

// ---------------- softmax attention, UB queries per block (K/V reuse), dynamic smem ----------------
__global__ void attn_kernel(const float* __restrict__ q, const float* __restrict__ k,
                            const float* __restrict__ v, const int* __restrict__ top,
                            float* __restrict__ upd, int L, int U, int nub) {
    extern __shared__ float smdyn[];
    float* s   = smdyn;            // UB * L
    float* qs  = s + UB * L;       // UB * 64
    float* red = qs + UB * 64;     // UB * 128
    int blk = blockIdx.x;
    int ub = blk % nub;
    int bh = blk / nub;
    int h = bh % NH, b = bh / NH;
    int tid = threadIdx.x; // 128
    int u0 = ub * UB;
    int nq = U - u0; if (nq > UB) nq = UB;

    for (int t = tid; t < UB * 64; t += 128) {
        int qq = t >> 6, d = t & 63;
        float val = 0.0f;
        if (qq < nq) {
            int lq = top[bh * U + u0 + qq];
            val = q[(size_t)(b * L + lq) * DM + h * DH + d];
        }
        qs[qq * 64 + d] = val;
    }
    __syncthreads();

    float lmax[UB];
    #pragma unroll
    for (int qq = 0; qq < UB; qq++) lmax[qq] = -INFINITY;
    for (int l = tid; l < L; l += 128) {
        const float4* kp4 = (const float4*)(k + (size_t)(b * L + l) * DM + h * DH);
        float acc[UB] = {};
        #pragma unroll
        for (int d4 = 0; d4 < 16; d4++) {
            float4 kk = kp4[d4];
            #pragma unroll
            for (int qq = 0; qq < UB; qq++) {
                float4 qv = ((const float4*)(qs + qq * 64))[d4];
                acc[qq] += qv.x*kk.x + qv.y*kk.y + qv.z*kk.z + qv.w*kk.w;
            }
        }
        #pragma unroll
        for (int qq = 0; qq < UB; qq++) {
            float a = acc[qq] * 0.125f;
            s[qq * L + l] = a;
            lmax[qq] = fmaxf(lmax[qq], a);
        }
    }
    #pragma unroll
    for (int qq = 0; qq < UB; qq++) red[qq * 128 + tid] = lmax[qq];
    __syncthreads();
    for (int st = 64; st; st >>= 1) {
        if (tid < st) {
            #pragma unroll
            for (int qq = 0; qq < UB; qq++)
                red[qq * 128 + tid] = fmaxf(red[qq * 128 + tid], red[qq * 128 + tid + st]);
        }
        __syncthreads();
    }
    float mx[UB];
    #pragma unroll
    for (int qq = 0; qq < UB; qq++) mx[qq] = red[qq * 128];
    __syncthreads();

    float lsum[UB] = {};
    for (int l = tid; l < L; l += 128) {
        #pragma unroll
        for (int qq = 0; qq < UB; qq++) {
            float e = expf(s[qq * L + l] - mx[qq]);
            s[qq * L + l] = e;
            lsum[qq] += e;
        }
    }
    #pragma unroll
    for (int qq = 0; qq < UB; qq++) red[qq * 128 + tid] = lsum[qq];
    __syncthreads();
    for (int st = 64; st; st >>= 1) {
        if (tid < st) {
            #pragma unroll
            for (int qq = 0; qq < UB; qq++)
                red[qq * 128 + tid] += red[qq * 128 + tid + st];
        }
        __syncthreads();
    }
    float inv[UB];
    #pragma unroll
    for (int qq = 0; qq < UB; qq++) inv[qq] = 1.0f / red[qq * 128];
    __syncthreads();

    int d = tid & 63, halfid = tid >> 6;
    int l0 = halfid * (L >> 1), l1 = l0 + (L >> 1);
    float acc[UB] = {};
    for (int l = l0; l < l1; l++) {
        float vv = v[(size_t)(b * L + l) * DM + h * DH + d];
        #pragma unroll
        for (int qq = 0; qq < UB; qq++) acc[qq] += s[qq * L + l] * vv;
    }
    #pragma unroll
    for (int qq = 0; qq < UB; qq++) red[qq * 128 + tid] = acc[qq];
    __syncthreads();
    if (tid < 64) {
        for (int qq = 0; qq < nq; qq++)
            upd[(size_t)(bh * U + u0 + qq) * DH + tid] =
                (red[qq * 128 + tid] + red[qq * 128 + tid + 64]) * inv[qq];
    }
}

// ---------------- Wo projection: base + per-head correction GEMMs (all coalesced) ----------------
// base[b][n] = bo[n] + sum_c vm[b][c] * Wo[n][c]; warp-per-column, lane-coalesced.
__global__ void obase_kernel(const float* __restrict__ vm, const float* __restrict__ Wo,
                             const float* __restrict__ bo, float* __restrict__ base) {
    __shared__ float vs[DM];
    int b = blockIdx.y;
    int n0 = blockIdx.x * 16;
    int tid = threadIdx.x;  // 256
    for (int t = tid; t < DM; t += 256) vs[t] = vm[b * DM + t];
    __syncthreads();
    int w = tid >> 5, lane = tid & 31;
    #pragma unroll
    for (int rep = 0; rep < 2; rep++) {
        int n = n0 + w * 2 + rep;
        const float4* wp = (const float4*)(Wo + (size_t)n * DM);
        const float4* vp = (const float4*)vs;
        float acc = 0.0f;
        #pragma unroll
        for (int j = 0; j < 4; j++) {
            float4 ww = wp[lane + 32 * j];
            float4 vv = vp[lane + 32 * j];
            acc += ww.x*vv.x + ww.y*vv.y + ww.z*vv.z + ww.w*vv.w;
        }
        #pragma unroll
        for (int off = 16; off; off >>= 1) acc += __shfl_xor_sync(0xffffffffu, acc, off);
        if (lane == 0) base[b * DM + n] = acc + bo[n];
    }
}

// t1[b,l][n] = base[b][n]
__global__ void ofill_kernel(const float* __restrict__ base, float* __restrict__ t1, int L) {
    int i = blockIdx.x * blockDim.x + threadIdx.x;
    if (i >= B_ * L * DM) return;
    int n = i % DM;
    int b = i / (DM * L);
    t1[i] = base[b * DM + n];
}

// Per-head correction GEMM: C[r][n] = sum_d (upd-vm)[r][d] * Wo[n][h*64+d], 64x64 tiles,
// scatter-added into t1 rows top[bh,u]. grid (DM/64, ceil(B*U/64), NH), block 256.
__global__ void ocorr_kernel(const float* __restrict__ upd, const float* __restrict__ vm,
                             const float* __restrict__ Wo, const int* __restrict__ top,
                             float* __restrict__ t1, int L, int U) {
    __shared__ float Ad[64][66];
    __shared__ float Wd[64][66];
    int h = blockIdx.z;
    int mt = blockIdx.y;
    int n0 = blockIdx.x * 64;
    int tid = threadIdx.x;
    int BU = B_ * U;
    for (int t = tid; t < 64 * 64; t += 256) {
        int r = t >> 6, d = t & 63;
        int rr = mt * 64 + r;
        float val = 0.0f;
        if (rr < BU) {
            int b = rr / U, u = rr - b * U;
            int bh = b * NH + h;
            val = upd[(size_t)(bh * U + u) * DH + d] - vm[bh * DH + d];
        }
        Ad[r][d] = val;
    }
    for (int t = tid; t < 64 * 64; t += 256) {
        int c = t >> 6, d = t & 63;
        Wd[c][d] = Wo[(size_t)(n0 + c) * DM + h * DH + d];
    }
    __syncthreads();
    int ty = tid >> 4, tx = tid & 15;
    float acc[4][4] = {};
    for (int d = 0; d < 64; d++) {
        float a[4], w[4];
        #pragma unroll
        for (int i = 0; i < 4; i++) a[i] = Ad[ty + 16 * i][d];
        #pragma unroll
        for (int j = 0; j < 4; j++) w[j] = Wd[tx + 16 * j][d];
        #pragma unroll
        for (int i = 0; i < 4; i++)
            #pragma unroll
            for (int j = 0; j < 4; j++)
                acc[i][j] += a[i] * w[j];
    }
    #pragma unroll
    for (int i = 0; i < 4; i++) {
        int rr = mt * 64 + ty + 16 * i;
        if (rr >= BU) continue;
        int b = rr / U, u = rr - b * U;
        int l = top[(b * NH + h) * U + u];
        float* row = t1 + (size_t)(b * L + l) * DM + n0;
        #pragma unroll
        for (int j = 0; j < 4; j++)
            atomicAdd(row + tx + 16 * j, acc[i][j]);
    }
}

// ---------------- x = LayerNorm(x + t) ----------------
__global__ void addln_kernel(float* __restrict__ x, const float* __restrict__ t,
                             const float* __restrict__ g, const float* __restrict__ bb) {
    __shared__ float row[512];
    __shared__ float red[256];
    size_t r = blockIdx.x;
    int tid = threadIdx.x;
    float v0 = x[r * 512 + tid]       + (t ? t[r * 512 + tid]       : 0.0f);
    float v1 = x[r * 512 + tid + 256] + (t ? t[r * 512 + tid + 256] : 0.0f);
    row[tid] = v0; row[tid + 256] = v1;
    red[tid] = v0 + v1;
    __syncthreads();
    for (int s = 128; s; s >>= 1) { if (tid < s) red[tid] += red[tid + s]; __syncthreads(); }
    float mu = red[0] * (1.0f / 512.0f);
    __syncthreads();
    float d0 = row[tid] - mu, d1 = row[tid + 256] - mu;
    red[tid] = d0 * d0 + d1 * d1;
    __syncthreads();
    for (int s = 128; s; s >>= 1) { if (tid < s) red[tid] += red[tid + s]; __syncthreads(); }
    float rstd = rsqrtf(red[0] * (1.0f / 512.0f) + LNEPS);
    x[r * 512 + tid]       = d0 * rstd * g[tid]       + bb[tid];
    x[r * 512 + tid + 256] = d1 * rstd * g[tid + 256] + bb[tid + 256];
}

__global__ void rowmax_kernel(const float* __restrict__ x, float* __restrict__ outr, int L) {
    int b = blockIdx.x, c = threadIdx.x;
    float m = -INFINITY;
    for (int l = 0; l < L; l++) m = fmaxf(m, x[(size_t)(b * L + l) * DM + c]);
    outr[b * DM + c] = m;
}

__global__ void proj_kernel(const float* __restrict__ red, const float* __restrict__ pw,
                            const float* __restrict__ pb, float* __restrict__ out) {
    int w = threadIdx.x >> 5, lane = threadIdx.x & 31;
    int b = w >> 1, o = w & 1;
    float acc = 0.0f;
    for (int c = lane; c < DM; c += 32) acc += red[b * DM + c] * pw[o * DM + c];
    #pragma unroll
    for (int s = 16; s; s >>= 1) acc += __shfl_xor_sync(0xffffffffu, acc, s);
    if (lane == 0) out[b * 2 + o] = acc + pb[o];
}

// ---------------- host ----------------
extern "C" void kernel_launch(void* const* d_in, const int* in_sizes, int n_in,
                              void* d_out, int out_size) {
    (void)n_in; (void)out_size;
    const float* x_enc = (const float*)d_in[0];
    const float* tok_w = (const float*)d_in[1];
    const float *Wq, *Wk, *Wv, *Wo, *bq, *bk, *bv, *bo;
    if (in_sizes[5] > 10000) {
        Wq = (const float*)d_in[2]; Wk = (const float*)d_in[3];
        Wv = (const float*)d_in[4]; Wo = (const float*)d_in[5];
        bq = (const float*)d_in[6]; bk = (const float*)d_in[7];
        bv = (const float*)d_in[8]; bo = (const float*)d_in[9];
    } else {
        Wq = (const float*)d_in[2]; Wk = (const float*)d_in[3];
        Wv = (const float*)d_in[4]; bq = (const float*)d_in[5];
        bk = (const float*)d_in[6]; bv = (const float*)d_in[7];
        Wo = (const float*)d_in[8]; bo = (const float*)d_in[9];
    }
    const float* W1   = (const float*)d_in[10];
    const float* b1   = (const float*)d_in[11];
    const float* W2   = (const float*)d_in[12];
    const float* b2   = (const float*)d_in[13];
    const float* ln1g = (const float*)d_in[14];
    const float* ln1b = (const float*)d_in[15];
    const float* ln2g = (const float*)d_in[16];
    const float* ln2b = (const float*)d_in[17];
    const float* dcw  = (const float*)d_in[18];
    const float* dcb  = (const float*)d_in[19];
    const float* bng  = (const float*)d_in[20];
    const float* bnb  = (const float*)d_in[21];
    const float* lnfg = (const float*)d_in[22];
    const float* lnfb = (const float*)d_in[23];
    const float* pw   = (const float*)d_in[24];
    const float* pb   = (const float*)d_in[25];

    float *x, *q, *k, *v, *t1, *t2, *Mb, *vm, *upd, *redb, *baseb;
    int *idxb, *topb;
    cudaGetSymbolAddress((void**)&x,    g_x);
    cudaGetSymbolAddress((void**)&q,    g_q);
    cudaGetSymbolAddress((void**)&k,    g_k);
    cudaGetSymbolAddress((void**)&v,    g_v);
    cudaGetSymbolAddress((void**)&t1,   g_t1);
    cudaGetSymbolAddress((void**)&t2,   g_t2);
    cudaGetSymbolAddress((void**)&Mb,   g_M);
    cudaGetSymbolAddress((void**)&vm,   g_vm);
    cudaGetSymbolAddress((void**)&upd,  g_upd);
    cudaGetSymbolAddress((void**)&redb, g_red);
    cudaGetSymbolAddress((void**)&baseb,g_base);
    cudaGetSymbolAddress((void**)&idxb, g_idx);
    cudaGetSymbolAddress((void**)&topb, g_top);

    cudaFuncSetAttribute(attn_kernel, cudaFuncAttributeMaxDynamicSharedMemorySize, 73728);

    embed_kernel<<<(B_*SEQ*DM + 255) / 256, 256>>>(x_enc, tok_w, x);

    int L = SEQ;
    for (int i = 0; i < NL; i++) {
        int Mrows = B_ * L;
        dim3 gg(DM / 128, Mrows / 128);
        dim3 g3(DM / 128, Mrows / 128, 3);
        qkv_kernel<<<g3, 256>>>(x, Wq + i*DM*DM, Wk + i*DM*DM, Wv + i*DM*DM,
                                bq + i*DM, bk + i*DM, bv + i*DM,
                                q, k, v, Mrows, DM);

        int U = 5 * (int)ceil(log((double)L));
        if (U > L) U = L;

        unsigned f0, f1, c0, c1;
        tf2x32(0u, 42u, 0u, (unsigned)i, &f0, &f1);
        tf2x32(f0, f1, 0u, 1u, &c0, &c1);

        idx_kernel<<<(L*U + 255) / 256, 256>>>(idxb, L, U, c0, c1);
        m_kernel<<<(B_*NH*L/2*32 + 127) / 128, 128>>>(q, k, idxb, Mb, L, U);
        topk_kernel<<<B_*NH, 256>>>(Mb, topb, L, U);
        vmean_kernel<<<B_*NH, 256>>>(v, vm, L);
        int nub = (U + UB - 1) / UB;
        size_t smb = (size_t)UB * L * 4 + UB * 64 * 4 + UB * 128 * 4;
        attn_kernel<<<B_*NH*nub, 128, smb>>>(q, k, v, topb, upd, L, U, nub);

        // t1 = o @ Wo^T + bo via base broadcast + per-head correction GEMMs
        obase_kernel<<<dim3(32, B_), 256>>>(vm, Wo + i*DM*DM, bo + i*DM, baseb);
        ofill_kernel<<<(B_*L*DM + 255) / 256, 256>>>(baseb, t1, L);
        ocorr_kernel<<<dim3(DM/64, (B_*U + 63)/64, NH), 256>>>(upd, vm, Wo + i*DM*DM,
                                                               topb, t1, L, U);

        addln_kernel<<<Mrows, 256>>>(x, t1, ln1g + i*DM, ln1b + i*DM);
        gemm_kernel<<<gg, 256>>>(x, W1 + i*DM*DM, b1 + i*DM, t1, Mrows, DM, DM, 1);
        gemm_kernel<<<gg, 256>>>(t1, W2 + i*DM*DM, b2 + i*DM, t2, Mrows, DM, DM, 0);
        addln_kernel<<<Mrows, 256>>>(x, t2, ln2g + i*DM, ln2b + i*DM);

        if (i < NL - 1) {
            wtrans_kernel<<<(DM*DM + 255) / 256, 256>>>(dcw + (size_t)i*DM*DM*3, t2);
            convgemm_kernel<<<gg, 256>>>(x, t2, dcb + i*DM,
                                         bng + i*DM, bnb + i*DM, t1, L);
            int Lout = L / 2;
            pool_kernel<<<(B_*Lout*DM + 255) / 256, 256>>>(t1, x, L);
            L = Lout;
        }
    }

    addln_kernel<<<B_*L, 256>>>(x, (const float*)nullptr, lnfg, lnfb);
    rowmax_kernel<<<B_, 512>>>(x, redb, L);
    proj_kernel<<<1, 512>>>(redb, pw, pb, (float*)d_out);
}